// round 1
// baseline (speedup 1.0000x reference)
#include <cuda_runtime.h>
#include <math.h>

// Problem constants
#define SQ    2048
#define DM    1024
#define NH    16
#define DKH   64
#define NB    2
#define NTOK  (NB*SQ)   // 4096

// ---------------------------------------------------------------------------
// Scratch (no cudaMalloc allowed): Q,K,V in [B,H,S,DK], X in [B,S,D]
// ---------------------------------------------------------------------------
__device__ float g_Q[(size_t)NB*NH*SQ*DKH];
__device__ float g_K[(size_t)NB*NH*SQ*DKH];
__device__ float g_V[(size_t)NB*NH*SQ*DKH];
__device__ float g_X[(size_t)NTOK*DM];

// ---------------------------------------------------------------------------
// GEMM: C[m][n] = sum_k A[m][k] * W[n][k] + bias[n]
// A: [M=4096, K=1024] row-major, W: [N=1024, K=1024] row-major (Linear W.T)
// mode 0: C row-major [M,N]
// mode 1: scatter to [B,H,S,DK]  (m = b*S+s, n = h*DK+dk)
// 128x128 tile, BK=8, 8x8 per thread, 256 threads.
// ---------------------------------------------------------------------------
__global__ __launch_bounds__(256)
void gemm_nt_bias(const float* __restrict__ A, const float* __restrict__ W,
                  const float* __restrict__ bias, float* __restrict__ C, int mode)
{
    const int K = DM;
    const int N = DM;
    __shared__ float As[8][128];
    __shared__ float Ws[8][128];

    const int tid = threadIdx.x;
    const int tx  = tid & 15;     // 0..15
    const int ty  = tid >> 4;     // 0..15
    const int bx  = blockIdx.x;   // N tile
    const int by  = blockIdx.y;   // M tile

    const int loadRow = tid >> 1;        // 0..127
    const int loadCol = (tid & 1) * 4;   // 0 or 4

    const float* Ag = A + (size_t)(by*128 + loadRow)*K + loadCol;
    const float* Wg = W + (size_t)(bx*128 + loadRow)*K + loadCol;

    float acc[8][8];
    #pragma unroll
    for (int i = 0; i < 8; i++)
        #pragma unroll
        for (int j = 0; j < 8; j++) acc[i][j] = 0.0f;

    for (int kt = 0; kt < K; kt += 8) {
        float4 a4 = *(const float4*)(Ag + kt);
        float4 w4 = *(const float4*)(Wg + kt);
        As[loadCol+0][loadRow] = a4.x;
        As[loadCol+1][loadRow] = a4.y;
        As[loadCol+2][loadRow] = a4.z;
        As[loadCol+3][loadRow] = a4.w;
        Ws[loadCol+0][loadRow] = w4.x;
        Ws[loadCol+1][loadRow] = w4.y;
        Ws[loadCol+2][loadRow] = w4.z;
        Ws[loadCol+3][loadRow] = w4.w;
        __syncthreads();

        #pragma unroll
        for (int k = 0; k < 8; k++) {
            float4 ra0 = *(const float4*)&As[k][ty*8];
            float4 ra1 = *(const float4*)&As[k][ty*8 + 4];
            float4 rb0 = *(const float4*)&Ws[k][tx*8];
            float4 rb1 = *(const float4*)&Ws[k][tx*8 + 4];
            float ra[8] = {ra0.x, ra0.y, ra0.z, ra0.w, ra1.x, ra1.y, ra1.z, ra1.w};
            float rb[8] = {rb0.x, rb0.y, rb0.z, rb0.w, rb1.x, rb1.y, rb1.z, rb1.w};
            #pragma unroll
            for (int i = 0; i < 8; i++)
                #pragma unroll
                for (int j = 0; j < 8; j++)
                    acc[i][j] = fmaf(ra[i], rb[j], acc[i][j]);
        }
        __syncthreads();
    }

    // Epilogue
    #pragma unroll
    for (int i = 0; i < 8; i++) {
        int row = by*128 + ty*8 + i;
        #pragma unroll
        for (int j = 0; j < 8; j++) {
            int col = bx*128 + tx*8 + j;
            float v = acc[i][j] + bias[col];
            if (mode == 0) {
                C[(size_t)row*N + col] = v;
            } else {
                int b  = row >> 11;       // /S
                int s  = row & (SQ-1);
                int h  = col >> 6;        // /DK
                int dk = col & (DKH-1);
                C[(((size_t)b*NH + h)*SQ + s)*DKH + dk] = v;
            }
        }
    }
}

// ---------------------------------------------------------------------------
// Causal flash attention, fp32.
// Q,K,V: [B*H, S, DK].  X out: [B, S, D] with d = h*DK + dk.
// Block: 64 query rows x 64 key cols per iteration, 256 threads (16x16),
// each thread owns a 4x4 patch. Online softmax; row reductions via shfl
// over the 16-lane tx groups.
// ---------------------------------------------------------------------------
#define ATTN_SMEM (4*64*65*4)

__global__ __launch_bounds__(256)
void attn_kernel(const float* __restrict__ Q, const float* __restrict__ K,
                 const float* __restrict__ V, float* __restrict__ X)
{
    extern __shared__ float sm[];
    float (*Qs)[65] = (float (*)[65])(sm);
    float (*Ks)[65] = (float (*)[65])(sm + 64*65);
    float (*Vs)[65] = (float (*)[65])(sm + 2*64*65);
    float (*Ps)[65] = (float (*)[65])(sm + 3*64*65);

    const int qt  = blockIdx.x;      // query tile (64 rows)
    const int bh  = blockIdx.y;      // b*NH + h
    const int tid = threadIdx.x;
    const int tx  = tid & 15;
    const int ty  = tid >> 4;

    const float* Qg = Q + ((size_t)bh*SQ + (size_t)qt*64)*DKH;
    const float* Kg = K + (size_t)bh*SQ*DKH;
    const float* Vg = V + (size_t)bh*SQ*DKH;

    // Load Q tile (64x64): 1024 float4s, 4 per thread
    #pragma unroll
    for (int t = 0; t < 4; t++) {
        int idx = tid + t*256;
        int r   = idx >> 4;
        int c4  = (idx & 15) << 2;
        float4 v4 = *(const float4*)(Qg + (size_t)r*DKH + c4);
        Qs[r][c4+0] = v4.x; Qs[r][c4+1] = v4.y;
        Qs[r][c4+2] = v4.z; Qs[r][c4+3] = v4.w;
    }

    float m_i[4], l_i[4], o[4][4];
    #pragma unroll
    for (int i = 0; i < 4; i++) {
        m_i[i] = -INFINITY;
        l_i[i] = 0.0f;
        #pragma unroll
        for (int j = 0; j < 4; j++) o[i][j] = 0.0f;
    }

    const float scale = 0.125f;  // 1/sqrt(64)

    for (int kt = 0; kt <= qt; kt++) {
        __syncthreads();  // previous PV done reading Ks/Vs/Ps
        // Load K and V tiles (each 64x64)
        #pragma unroll
        for (int t = 0; t < 4; t++) {
            int idx = tid + t*256;
            int r   = idx >> 4;
            int c4  = (idx & 15) << 2;
            float4 kv = *(const float4*)(Kg + ((size_t)(kt*64 + r))*DKH + c4);
            Ks[r][c4+0] = kv.x; Ks[r][c4+1] = kv.y;
            Ks[r][c4+2] = kv.z; Ks[r][c4+3] = kv.w;
            float4 vv = *(const float4*)(Vg + ((size_t)(kt*64 + r))*DKH + c4);
            Vs[r][c4+0] = vv.x; Vs[r][c4+1] = vv.y;
            Vs[r][c4+2] = vv.z; Vs[r][c4+3] = vv.w;
        }
        __syncthreads();

        // S = Q K^T (4x4 per thread)
        float s[4][4];
        #pragma unroll
        for (int i = 0; i < 4; i++)
            #pragma unroll
            for (int j = 0; j < 4; j++) s[i][j] = 0.0f;

        #pragma unroll 8
        for (int d = 0; d < 64; d++) {
            float qv[4], kv[4];
            #pragma unroll
            for (int i = 0; i < 4; i++) qv[i] = Qs[ty*4+i][d];
            #pragma unroll
            for (int j = 0; j < 4; j++) kv[j] = Ks[tx*4+j][d];
            #pragma unroll
            for (int i = 0; i < 4; i++)
                #pragma unroll
                for (int j = 0; j < 4; j++)
                    s[i][j] = fmaf(qv[i], kv[j], s[i][j]);
        }

        // scale + causal mask (only the diagonal tile needs element masking)
        #pragma unroll
        for (int i = 0; i < 4; i++)
            #pragma unroll
            for (int j = 0; j < 4; j++) {
                s[i][j] *= scale;
                if (kt == qt && (tx*4 + j) > (ty*4 + i)) s[i][j] = -1e30f;
            }

        // Online softmax (per row; rows live in 16-lane tx groups)
        #pragma unroll
        for (int i = 0; i < 4; i++) {
            float mloc = s[i][0];
            #pragma unroll
            for (int j = 1; j < 4; j++) mloc = fmaxf(mloc, s[i][j]);
            #pragma unroll
            for (int off = 8; off >= 1; off >>= 1)
                mloc = fmaxf(mloc, __shfl_xor_sync(0xffffffffu, mloc, off));
            float mnew  = fmaxf(m_i[i], mloc);
            float alpha = __expf(m_i[i] - mnew);
            float lloc  = 0.0f;
            #pragma unroll
            for (int j = 0; j < 4; j++) {
                s[i][j] = __expf(s[i][j] - mnew);
                lloc += s[i][j];
            }
            #pragma unroll
            for (int off = 8; off >= 1; off >>= 1)
                lloc += __shfl_xor_sync(0xffffffffu, lloc, off);
            l_i[i] = l_i[i]*alpha + lloc;
            m_i[i] = mnew;
            #pragma unroll
            for (int j = 0; j < 4; j++) o[i][j] *= alpha;
            #pragma unroll
            for (int j = 0; j < 4; j++) Ps[ty*4+i][tx*4+j] = s[i][j];
        }
        __syncthreads();

        // O += P @ V
        #pragma unroll 8
        for (int kk = 0; kk < 64; kk++) {
            float pv[4], vv[4];
            #pragma unroll
            for (int i = 0; i < 4; i++) pv[i] = Ps[ty*4+i][kk];
            #pragma unroll
            for (int j = 0; j < 4; j++) vv[j] = Vs[kk][tx*4+j];
            #pragma unroll
            for (int i = 0; i < 4; i++)
                #pragma unroll
                for (int j = 0; j < 4; j++)
                    o[i][j] = fmaf(pv[i], vv[j], o[i][j]);
        }
    }

    // Finalize and write to X[B,S,D]
    const int b = bh / NH;
    const int h = bh % NH;
    #pragma unroll
    for (int i = 0; i < 4; i++) {
        int srow = qt*64 + ty*4 + i;
        float inv = 1.0f / l_i[i];
        float4 r;
        r.x = o[i][0]*inv; r.y = o[i][1]*inv;
        r.z = o[i][2]*inv; r.w = o[i][3]*inv;
        *(float4*)(X + ((size_t)(b*SQ + srow))*DM + h*DKH + tx*4) = r;
    }
}

// ---------------------------------------------------------------------------
// Launch
// ---------------------------------------------------------------------------
extern "C" void kernel_launch(void* const* d_in, const int* in_sizes, int n_in,
                              void* d_out, int out_size)
{
    (void)in_sizes; (void)n_in; (void)out_size;
    const float* q  = (const float*)d_in[0];
    const float* k  = (const float*)d_in[1];
    const float* v  = (const float*)d_in[2];
    // d_in[3] = mask (int32, causal) — implied by kernel structure
    const float* Wq = (const float*)d_in[4];
    const float* bq = (const float*)d_in[5];
    const float* Wk = (const float*)d_in[6];
    const float* bk = (const float*)d_in[7];
    const float* Wv = (const float*)d_in[8];
    const float* bv = (const float*)d_in[9];
    const float* Wo = (const float*)d_in[10];
    const float* bo = (const float*)d_in[11];
    float* out = (float*)d_out;

    float *Qp, *Kp, *Vp, *Xp;
    cudaGetSymbolAddress((void**)&Qp, g_Q);
    cudaGetSymbolAddress((void**)&Kp, g_K);
    cudaGetSymbolAddress((void**)&Vp, g_V);
    cudaGetSymbolAddress((void**)&Xp, g_X);

    cudaFuncSetAttribute(attn_kernel,
                         cudaFuncAttributeMaxDynamicSharedMemorySize, ATTN_SMEM);

    dim3 gg(DM/128, NTOK/128);   // (8, 32)
    gemm_nt_bias<<<gg, 256>>>(q, Wq, bq, Qp, 1);
    gemm_nt_bias<<<gg, 256>>>(k, Wk, bk, Kp, 1);
    gemm_nt_bias<<<gg, 256>>>(v, Wv, bv, Vp, 1);
    attn_kernel<<<dim3(SQ/64, NB*NH), 256, ATTN_SMEM>>>(Qp, Kp, Vp, Xp);
    gemm_nt_bias<<<gg, 256>>>(Xp, Wo, bo, out, 0);
}

// round 3
// speedup vs baseline: 1.5366x; 1.5366x over previous
#include <cuda_runtime.h>
#include <math.h>
#include <cstdint>

// Problem constants
#define SQ    2048
#define DM    1024
#define NH    16
#define DKH   64
#define NB    2
#define NTOK  (NB*SQ)   // 4096

// ---------------------------------------------------------------------------
// Scratch (no cudaMalloc allowed)
// ---------------------------------------------------------------------------
__device__ float g_Q[(size_t)NB*NH*SQ*DKH];
__device__ float g_K[(size_t)NB*NH*SQ*DKH];
__device__ float g_V[(size_t)NB*NH*SQ*DKH];
__device__ float g_X[(size_t)NTOK*DM];

// ---------------------------------------------------------------------------
// Helpers
// ---------------------------------------------------------------------------
__device__ __forceinline__ uint32_t f2tf32(float f) {
    uint32_t r;
    asm("cvt.rna.tf32.f32 %0, %1;" : "=r"(r) : "f"(f));
    return r;
}

__device__ __forceinline__ void mma_tf32(float c[4], const uint32_t a[4],
                                         const uint32_t b[2]) {
    asm volatile(
        "mma.sync.aligned.m16n8k8.row.col.f32.tf32.tf32.f32 "
        "{%0,%1,%2,%3}, {%4,%5,%6,%7}, {%8,%9}, {%0,%1,%2,%3};"
        : "+f"(c[0]), "+f"(c[1]), "+f"(c[2]), "+f"(c[3])
        : "r"(a[0]), "r"(a[1]), "r"(a[2]), "r"(a[3]),
          "r"(b[0]), "r"(b[1]));
}

// ---------------------------------------------------------------------------
// tf32 mma.sync GEMM: C[m][n] = sum_k A[m][k]*W[n][k] + bias[n]
// A: [4096,1024] rm, W: [1024,1024] rm (both K-major => row.col works directly:
// A fragment rows are M, cols K; B fragment is K x N col-major = W[n][k]).
// CTA: 128x128 tile, BK=32, 256 threads (8 warps, 2x4 warp grid, 64x32/warp).
// mode 0: C row-major [M,N]; mode 1: scatter to [B,H,S,DK].
// ---------------------------------------------------------------------------
#define BM 128
#define BN 128
#define BK 32
#define SA 136                         // padded k-row stride in words
#define A_STAGE (BK*SA)                // 4352 words
#define GEMM_SMEM_WORDS (4*A_STAGE)    // A x2 stages + B x2 stages
#define GEMM_SMEM (GEMM_SMEM_WORDS*4)  // 69632 bytes
#define GEMM_NT (DM/BK)                // 32 k-tiles

__global__ __launch_bounds__(256)
void gemm_tf32(const float* __restrict__ A, const float* __restrict__ W,
               const float* __restrict__ bias, float* __restrict__ C, int mode)
{
    extern __shared__ uint32_t sh[];
    uint32_t* As = sh;                 // [2][BK][SA]
    uint32_t* Bs = sh + 2*A_STAGE;     // [2][BK][SA]

    const int tid    = threadIdx.x;
    const int wid    = tid >> 5;
    const int lane   = tid & 31;
    const int gid    = lane >> 2;      // 0..7
    const int tig    = lane & 3;       // 0..3
    const int warp_m = (wid >> 2) * 64;  // 0 or 64
    const int warp_n = (wid & 3) * 32;   // 0,32,64,96
    const int bx     = blockIdx.x;     // N tile
    const int by     = blockIdx.y;     // M tile

    // Global load mapping: 2 threads per row, 16 floats each (4 float4)
    const int lrow  = tid >> 1;          // 0..127
    const int lcol0 = (tid & 1) * 16;    // 0 or 16
    const float* Ag = A + (size_t)(by*BM + lrow)*DM + lcol0;
    const float* Wg = W + (size_t)(bx*BN + lrow)*DM + lcol0;

    float4 fa[4], fw[4];
    auto ldg_tile = [&](int kt) {
        const float* ap = Ag + kt*BK;
        const float* wp = Wg + kt*BK;
        #pragma unroll
        for (int i = 0; i < 4; i++) {
            fa[i] = *(const float4*)(ap + i*4);
            fw[i] = *(const float4*)(wp + i*4);
        }
    };
    auto sts_tile = [&](int stage) {
        uint32_t* a = As + stage*A_STAGE;
        uint32_t* b = Bs + stage*A_STAGE;
        #pragma unroll
        for (int i = 0; i < 4; i++) {
            int k = lcol0 + i*4;
            a[(k+0)*SA + lrow] = f2tf32(fa[i].x);
            a[(k+1)*SA + lrow] = f2tf32(fa[i].y);
            a[(k+2)*SA + lrow] = f2tf32(fa[i].z);
            a[(k+3)*SA + lrow] = f2tf32(fa[i].w);
            b[(k+0)*SA + lrow] = f2tf32(fw[i].x);
            b[(k+1)*SA + lrow] = f2tf32(fw[i].y);
            b[(k+2)*SA + lrow] = f2tf32(fw[i].z);
            b[(k+3)*SA + lrow] = f2tf32(fw[i].w);
        }
    };

    float acc[4][4][4];
    #pragma unroll
    for (int i = 0; i < 4; i++)
        #pragma unroll
        for (int j = 0; j < 4; j++)
            #pragma unroll
            for (int r = 0; r < 4; r++) acc[i][j][r] = 0.0f;

    ldg_tile(0);
    sts_tile(0);
    __syncthreads();

    for (int kt = 0; kt < GEMM_NT; kt++) {
        if (kt + 1 < GEMM_NT) ldg_tile(kt + 1);

        const uint32_t* a = As + (kt & 1)*A_STAGE;
        const uint32_t* b = Bs + (kt & 1)*A_STAGE;
        #pragma unroll
        for (int ks = 0; ks < BK; ks += 8) {
            uint32_t af[4][4], bf[4][2];
            #pragma unroll
            for (int i = 0; i < 4; i++) {
                int r0 = warp_m + i*16 + gid;
                af[i][0] = a[(ks+tig  )*SA + r0];
                af[i][1] = a[(ks+tig  )*SA + r0 + 8];
                af[i][2] = a[(ks+tig+4)*SA + r0];
                af[i][3] = a[(ks+tig+4)*SA + r0 + 8];
            }
            #pragma unroll
            for (int j = 0; j < 4; j++) {
                int n = warp_n + j*8 + gid;
                bf[j][0] = b[(ks+tig  )*SA + n];
                bf[j][1] = b[(ks+tig+4)*SA + n];
            }
            #pragma unroll
            for (int i = 0; i < 4; i++)
                #pragma unroll
                for (int j = 0; j < 4; j++)
                    mma_tf32(acc[i][j], af[i], bf[j]);
        }

        if (kt + 1 < GEMM_NT) sts_tile((kt + 1) & 1);
        __syncthreads();
    }

    // Epilogue: add bias, store (float2 per fragment row)
    #pragma unroll
    for (int i = 0; i < 4; i++) {
        #pragma unroll
        for (int j = 0; j < 4; j++) {
            int row0 = by*BM + warp_m + i*16 + gid;
            int col  = bx*BN + warp_n + j*8 + tig*2;
            float bx0 = bias[col], bx1 = bias[col+1];
            float2 v0 = make_float2(acc[i][j][0] + bx0, acc[i][j][1] + bx1);
            float2 v1 = make_float2(acc[i][j][2] + bx0, acc[i][j][3] + bx1);
            if (mode == 0) {
                *(float2*)(C + (size_t)row0*DM + col)     = v0;
                *(float2*)(C + (size_t)(row0+8)*DM + col) = v1;
            } else {
                int h  = col >> 6;
                int dk = col & (DKH-1);
                int b0 = row0 >> 11, s0 = row0 & (SQ-1);
                *(float2*)(C + (((size_t)(b0*NH + h)*SQ) + s0)*DKH + dk) = v0;
                int row1 = row0 + 8;
                int b1 = row1 >> 11, s1 = row1 & (SQ-1);
                *(float2*)(C + (((size_t)(b1*NH + h)*SQ) + s1)*DKH + dk) = v1;
            }
        }
    }
}

// ---------------------------------------------------------------------------
// Causal flash attention, fp32 (unchanged from R1 passing version).
// ---------------------------------------------------------------------------
#define ATTN_SMEM (4*64*65*4)

__global__ __launch_bounds__(256)
void attn_kernel(const float* __restrict__ Q, const float* __restrict__ K,
                 const float* __restrict__ V, float* __restrict__ X)
{
    extern __shared__ float smf[];
    float (*Qs)[65] = (float (*)[65])(smf);
    float (*Ks)[65] = (float (*)[65])(smf + 64*65);
    float (*Vs)[65] = (float (*)[65])(smf + 2*64*65);
    float (*Ps)[65] = (float (*)[65])(smf + 3*64*65);

    const int qt  = blockIdx.x;
    const int bh  = blockIdx.y;
    const int tid = threadIdx.x;
    const int tx  = tid & 15;
    const int ty  = tid >> 4;

    const float* Qg = Q + ((size_t)bh*SQ + (size_t)qt*64)*DKH;
    const float* Kg = K + (size_t)bh*SQ*DKH;
    const float* Vg = V + (size_t)bh*SQ*DKH;

    #pragma unroll
    for (int t = 0; t < 4; t++) {
        int idx = tid + t*256;
        int r   = idx >> 4;
        int c4  = (idx & 15) << 2;
        float4 v4 = *(const float4*)(Qg + (size_t)r*DKH + c4);
        Qs[r][c4+0] = v4.x; Qs[r][c4+1] = v4.y;
        Qs[r][c4+2] = v4.z; Qs[r][c4+3] = v4.w;
    }

    float m_i[4], l_i[4], o[4][4];
    #pragma unroll
    for (int i = 0; i < 4; i++) {
        m_i[i] = -INFINITY;
        l_i[i] = 0.0f;
        #pragma unroll
        for (int j = 0; j < 4; j++) o[i][j] = 0.0f;
    }

    const float scale = 0.125f;

    for (int kt = 0; kt <= qt; kt++) {
        __syncthreads();
        #pragma unroll
        for (int t = 0; t < 4; t++) {
            int idx = tid + t*256;
            int r   = idx >> 4;
            int c4  = (idx & 15) << 2;
            float4 kv = *(const float4*)(Kg + ((size_t)(kt*64 + r))*DKH + c4);
            Ks[r][c4+0] = kv.x; Ks[r][c4+1] = kv.y;
            Ks[r][c4+2] = kv.z; Ks[r][c4+3] = kv.w;
            float4 vv = *(const float4*)(Vg + ((size_t)(kt*64 + r))*DKH + c4);
            Vs[r][c4+0] = vv.x; Vs[r][c4+1] = vv.y;
            Vs[r][c4+2] = vv.z; Vs[r][c4+3] = vv.w;
        }
        __syncthreads();

        float s[4][4];
        #pragma unroll
        for (int i = 0; i < 4; i++)
            #pragma unroll
            for (int j = 0; j < 4; j++) s[i][j] = 0.0f;

        #pragma unroll 8
        for (int d = 0; d < 64; d++) {
            float qv[4], kv[4];
            #pragma unroll
            for (int i = 0; i < 4; i++) qv[i] = Qs[ty*4+i][d];
            #pragma unroll
            for (int j = 0; j < 4; j++) kv[j] = Ks[tx*4+j][d];
            #pragma unroll
            for (int i = 0; i < 4; i++)
                #pragma unroll
                for (int j = 0; j < 4; j++)
                    s[i][j] = fmaf(qv[i], kv[j], s[i][j]);
        }

        #pragma unroll
        for (int i = 0; i < 4; i++)
            #pragma unroll
            for (int j = 0; j < 4; j++) {
                s[i][j] *= scale;
                if (kt == qt && (tx*4 + j) > (ty*4 + i)) s[i][j] = -1e30f;
            }

        #pragma unroll
        for (int i = 0; i < 4; i++) {
            float mloc = s[i][0];
            #pragma unroll
            for (int j = 1; j < 4; j++) mloc = fmaxf(mloc, s[i][j]);
            #pragma unroll
            for (int off = 8; off >= 1; off >>= 1)
                mloc = fmaxf(mloc, __shfl_xor_sync(0xffffffffu, mloc, off));
            float mnew  = fmaxf(m_i[i], mloc);
            float alpha = __expf(m_i[i] - mnew);
            float lloc  = 0.0f;
            #pragma unroll
            for (int j = 0; j < 4; j++) {
                s[i][j] = __expf(s[i][j] - mnew);
                lloc += s[i][j];
            }
            #pragma unroll
            for (int off = 8; off >= 1; off >>= 1)
                lloc += __shfl_xor_sync(0xffffffffu, lloc, off);
            l_i[i] = l_i[i]*alpha + lloc;
            m_i[i] = mnew;
            #pragma unroll
            for (int j = 0; j < 4; j++) o[i][j] *= alpha;
            #pragma unroll
            for (int j = 0; j < 4; j++) Ps[ty*4+i][tx*4+j] = s[i][j];
        }
        __syncthreads();

        #pragma unroll 8
        for (int kk = 0; kk < 64; kk++) {
            float pv[4], vv[4];
            #pragma unroll
            for (int i = 0; i < 4; i++) pv[i] = Ps[ty*4+i][kk];
            #pragma unroll
            for (int j = 0; j < 4; j++) vv[j] = Vs[kk][tx*4+j];
            #pragma unroll
            for (int i = 0; i < 4; i++)
                #pragma unroll
                for (int j = 0; j < 4; j++)
                    o[i][j] = fmaf(pv[i], vv[j], o[i][j]);
        }
    }

    const int b = bh / NH;
    const int h = bh % NH;
    #pragma unroll
    for (int i = 0; i < 4; i++) {
        int srow = qt*64 + ty*4 + i;
        float inv = 1.0f / l_i[i];
        float4 r;
        r.x = o[i][0]*inv; r.y = o[i][1]*inv;
        r.z = o[i][2]*inv; r.w = o[i][3]*inv;
        *(float4*)(X + ((size_t)(b*SQ + srow))*DM + h*DKH + tx*4) = r;
    }
}

// ---------------------------------------------------------------------------
// Launch
// ---------------------------------------------------------------------------
extern "C" void kernel_launch(void* const* d_in, const int* in_sizes, int n_in,
                              void* d_out, int out_size)
{
    (void)in_sizes; (void)n_in; (void)out_size;
    const float* q  = (const float*)d_in[0];
    const float* k  = (const float*)d_in[1];
    const float* v  = (const float*)d_in[2];
    const float* Wq = (const float*)d_in[4];
    const float* bq = (const float*)d_in[5];
    const float* Wk = (const float*)d_in[6];
    const float* bk = (const float*)d_in[7];
    const float* Wv = (const float*)d_in[8];
    const float* bv = (const float*)d_in[9];
    const float* Wo = (const float*)d_in[10];
    const float* bo = (const float*)d_in[11];
    float* out = (float*)d_out;

    float *Qp, *Kp, *Vp, *Xp;
    cudaGetSymbolAddress((void**)&Qp, g_Q);
    cudaGetSymbolAddress((void**)&Kp, g_K);
    cudaGetSymbolAddress((void**)&Vp, g_V);
    cudaGetSymbolAddress((void**)&Xp, g_X);

    cudaFuncSetAttribute(attn_kernel,
                         cudaFuncAttributeMaxDynamicSharedMemorySize, ATTN_SMEM);
    cudaFuncSetAttribute(gemm_tf32,
                         cudaFuncAttributeMaxDynamicSharedMemorySize, GEMM_SMEM);

    dim3 gg(DM/BN, NTOK/BM);   // (8, 32)
    gemm_tf32<<<gg, 256, GEMM_SMEM>>>(q, Wq, bq, Qp, 1);
    gemm_tf32<<<gg, 256, GEMM_SMEM>>>(k, Wk, bk, Kp, 1);
    gemm_tf32<<<gg, 256, GEMM_SMEM>>>(v, Wv, bv, Vp, 1);
    attn_kernel<<<dim3(SQ/64, NB*NH), 256, ATTN_SMEM>>>(Qp, Kp, Vp, Xp);
    gemm_tf32<<<gg, 256, GEMM_SMEM>>>(Xp, Wo, bo, out, 0);
}

// round 4
// speedup vs baseline: 2.1890x; 1.4246x over previous
#include <cuda_runtime.h>
#include <math.h>
#include <cstdint>

// Problem constants
#define SQ    2048
#define DM    1024
#define NH    16
#define DKH   64
#define NB    2
#define NTOK  (NB*SQ)   // 4096

// ---------------------------------------------------------------------------
// Scratch (no cudaMalloc allowed)
// ---------------------------------------------------------------------------
__device__ float g_Q[(size_t)NB*NH*SQ*DKH];
__device__ float g_K[(size_t)NB*NH*SQ*DKH];
__device__ float g_V[(size_t)NB*NH*SQ*DKH];
__device__ float g_X[(size_t)NTOK*DM];

// ---------------------------------------------------------------------------
// Helpers
// ---------------------------------------------------------------------------
__device__ __forceinline__ uint32_t f2tf32(float f) {
    uint32_t r;
    asm("cvt.rna.tf32.f32 %0, %1;" : "=r"(r) : "f"(f));
    return r;
}
__device__ __forceinline__ float ex2(float x) {
    float y;
    asm("ex2.approx.f32 %0, %1;" : "=f"(y) : "f"(x));
    return y;
}
__device__ __forceinline__ void mma_tf32(float c[4], const uint32_t a[4],
                                         const uint32_t b0, const uint32_t b1) {
    asm volatile(
        "mma.sync.aligned.m16n8k8.row.col.f32.tf32.tf32.f32 "
        "{%0,%1,%2,%3}, {%4,%5,%6,%7}, {%8,%9}, {%0,%1,%2,%3};"
        : "+f"(c[0]), "+f"(c[1]), "+f"(c[2]), "+f"(c[3])
        : "r"(a[0]), "r"(a[1]), "r"(a[2]), "r"(a[3]),
          "r"(b0), "r"(b1));
}

// ---------------------------------------------------------------------------
// tf32 mma.sync GEMM (unchanged from R3 passing version)
// ---------------------------------------------------------------------------
#define BM 128
#define BN 128
#define BK 32
#define SA 136
#define A_STAGE (BK*SA)
#define GEMM_SMEM_WORDS (4*A_STAGE)
#define GEMM_SMEM (GEMM_SMEM_WORDS*4)
#define GEMM_NT (DM/BK)

__global__ __launch_bounds__(256)
void gemm_tf32(const float* __restrict__ A, const float* __restrict__ W,
               const float* __restrict__ bias, float* __restrict__ C, int mode)
{
    extern __shared__ uint32_t sh[];
    uint32_t* As = sh;
    uint32_t* Bs = sh + 2*A_STAGE;

    const int tid    = threadIdx.x;
    const int wid    = tid >> 5;
    const int lane   = tid & 31;
    const int gid    = lane >> 2;
    const int tig    = lane & 3;
    const int warp_m = (wid >> 2) * 64;
    const int warp_n = (wid & 3) * 32;
    const int bx     = blockIdx.x;
    const int by     = blockIdx.y;

    const int lrow  = tid >> 1;
    const int lcol0 = (tid & 1) * 16;
    const float* Ag = A + (size_t)(by*BM + lrow)*DM + lcol0;
    const float* Wg = W + (size_t)(bx*BN + lrow)*DM + lcol0;

    float4 fa[4], fw[4];
    auto ldg_tile = [&](int kt) {
        const float* ap = Ag + kt*BK;
        const float* wp = Wg + kt*BK;
        #pragma unroll
        for (int i = 0; i < 4; i++) {
            fa[i] = *(const float4*)(ap + i*4);
            fw[i] = *(const float4*)(wp + i*4);
        }
    };
    auto sts_tile = [&](int stage) {
        uint32_t* a = As + stage*A_STAGE;
        uint32_t* b = Bs + stage*A_STAGE;
        #pragma unroll
        for (int i = 0; i < 4; i++) {
            int k = lcol0 + i*4;
            a[(k+0)*SA + lrow] = f2tf32(fa[i].x);
            a[(k+1)*SA + lrow] = f2tf32(fa[i].y);
            a[(k+2)*SA + lrow] = f2tf32(fa[i].z);
            a[(k+3)*SA + lrow] = f2tf32(fa[i].w);
            b[(k+0)*SA + lrow] = f2tf32(fw[i].x);
            b[(k+1)*SA + lrow] = f2tf32(fw[i].y);
            b[(k+2)*SA + lrow] = f2tf32(fw[i].z);
            b[(k+3)*SA + lrow] = f2tf32(fw[i].w);
        }
    };

    float acc[4][4][4];
    #pragma unroll
    for (int i = 0; i < 4; i++)
        #pragma unroll
        for (int j = 0; j < 4; j++)
            #pragma unroll
            for (int r = 0; r < 4; r++) acc[i][j][r] = 0.0f;

    ldg_tile(0);
    sts_tile(0);
    __syncthreads();

    for (int kt = 0; kt < GEMM_NT; kt++) {
        if (kt + 1 < GEMM_NT) ldg_tile(kt + 1);

        const uint32_t* a = As + (kt & 1)*A_STAGE;
        const uint32_t* b = Bs + (kt & 1)*A_STAGE;
        #pragma unroll
        for (int ks = 0; ks < BK; ks += 8) {
            uint32_t af[4][4], bf[4][2];
            #pragma unroll
            for (int i = 0; i < 4; i++) {
                int r0 = warp_m + i*16 + gid;
                af[i][0] = a[(ks+tig  )*SA + r0];
                af[i][1] = a[(ks+tig  )*SA + r0 + 8];
                af[i][2] = a[(ks+tig+4)*SA + r0];
                af[i][3] = a[(ks+tig+4)*SA + r0 + 8];
            }
            #pragma unroll
            for (int j = 0; j < 4; j++) {
                int n = warp_n + j*8 + gid;
                bf[j][0] = b[(ks+tig  )*SA + n];
                bf[j][1] = b[(ks+tig+4)*SA + n];
            }
            #pragma unroll
            for (int i = 0; i < 4; i++)
                #pragma unroll
                for (int j = 0; j < 4; j++)
                    mma_tf32(acc[i][j], af[i], bf[j][0], bf[j][1]);
        }

        if (kt + 1 < GEMM_NT) sts_tile((kt + 1) & 1);
        __syncthreads();
    }

    #pragma unroll
    for (int i = 0; i < 4; i++) {
        #pragma unroll
        for (int j = 0; j < 4; j++) {
            int row0 = by*BM + warp_m + i*16 + gid;
            int col  = bx*BN + warp_n + j*8 + tig*2;
            float bx0 = bias[col], bx1 = bias[col+1];
            float2 v0 = make_float2(acc[i][j][0] + bx0, acc[i][j][1] + bx1);
            float2 v1 = make_float2(acc[i][j][2] + bx0, acc[i][j][3] + bx1);
            if (mode == 0) {
                *(float2*)(C + (size_t)row0*DM + col)     = v0;
                *(float2*)(C + (size_t)(row0+8)*DM + col) = v1;
            } else {
                int h  = col >> 6;
                int dk = col & (DKH-1);
                int b0 = row0 >> 11, s0 = row0 & (SQ-1);
                *(float2*)(C + (((size_t)(b0*NH + h)*SQ) + s0)*DKH + dk) = v0;
                int row1 = row0 + 8;
                int b1 = row1 >> 11, s1 = row1 & (SQ-1);
                *(float2*)(C + (((size_t)(b1*NH + h)*SQ) + s1)*DKH + dk) = v1;
            }
        }
    }
}

// ---------------------------------------------------------------------------
// Tensor-core causal flash attention (tf32 mma.sync, K/V residual-split).
// CTA: 128 q-rows x 64-key tiles, 8 warps (each warp: m16 x all 64 keys).
// K smem transposed [dk][key], V natural [key][dk], stride 72 (conflict-free
// fragment LDS since 72 % 32 == 8). Q fragments in registers.
// ---------------------------------------------------------------------------
#define AT_STRIDE 72
#define AT_TILE   (64*AT_STRIDE)           // words per array
#define ATTN_SMEM (4*AT_TILE*4)            // Khi,Klo,Vhi,Vlo = 73728 B
#define COEF 0.18033688f                   // 0.125 * log2(e)

__global__ __launch_bounds__(256, 1)
void attn_tc(const float* __restrict__ Q, const float* __restrict__ K,
             const float* __restrict__ V, float* __restrict__ X)
{
    extern __shared__ uint32_t sh[];
    uint32_t* Khi = sh;
    uint32_t* Klo = sh + AT_TILE;
    uint32_t* Vhi = sh + 2*AT_TILE;
    uint32_t* Vlo = sh + 3*AT_TILE;

    const int qt   = (int)gridDim.x - 1 - (int)blockIdx.x;  // heavy tiles first
    const int bh   = blockIdx.y;
    const int tid  = threadIdx.x;
    const int wid  = tid >> 5;
    const int lane = tid & 31;
    const int gid  = lane >> 2;
    const int tig  = lane & 3;

    const int row0 = qt*128 + wid*16 + gid;
    const int row1 = row0 + 8;

    // Q fragments in registers (tf32)
    uint32_t qf[8][4];
    {
        const float* q0 = Q + ((size_t)bh*SQ + row0)*DKH;
        const float* q1 = Q + ((size_t)bh*SQ + row1)*DKH;
        #pragma unroll
        for (int c = 0; c < 8; c++) {
            qf[c][0] = f2tf32(q0[8*c + tig]);
            qf[c][1] = f2tf32(q1[8*c + tig]);
            qf[c][2] = f2tf32(q0[8*c + tig + 4]);
            qf[c][3] = f2tf32(q1[8*c + tig + 4]);
        }
    }

    float o[8][4];
    #pragma unroll
    for (int j = 0; j < 8; j++)
        #pragma unroll
        for (int r = 0; r < 4; r++) o[j][r] = 0.0f;
    float m0 = -INFINITY, m1 = -INFINITY, l0 = 0.0f, l1 = 0.0f;

    const int tkey = tid >> 2;        // 0..63 (key row to load)
    const int tseg = tid & 3;         // 16-float segment
    const float* Kg = K + (size_t)bh*SQ*DKH;
    const float* Vg = V + (size_t)bh*SQ*DKH;

    const int ktmax = 2*qt + 1;
    for (int kt = 0; kt <= ktmax; kt++) {
        __syncthreads();
        // Load K (transposed) and V tiles, split into hi+lo tf32
        {
            const float* kr = Kg + ((size_t)(kt*64 + tkey))*DKH + tseg*16;
            const float* vr = Vg + ((size_t)(kt*64 + tkey))*DKH + tseg*16;
            #pragma unroll
            for (int i = 0; i < 4; i++) {
                float4 kv = *(const float4*)(kr + 4*i);
                float4 vv = *(const float4*)(vr + 4*i);
                const float ke[4] = {kv.x, kv.y, kv.z, kv.w};
                const float ve[4] = {vv.x, vv.y, vv.z, vv.w};
                #pragma unroll
                for (int u = 0; u < 4; u++) {
                    int dk = tseg*16 + 4*i + u;
                    uint32_t hi = f2tf32(ke[u]);
                    uint32_t lo = f2tf32(ke[u] - __uint_as_float(hi));
                    Khi[dk*AT_STRIDE + tkey] = hi;
                    Klo[dk*AT_STRIDE + tkey] = lo;
                    uint32_t vh = f2tf32(ve[u]);
                    uint32_t vl = f2tf32(ve[u] - __uint_as_float(vh));
                    Vhi[tkey*AT_STRIDE + dk] = vh;
                    Vlo[tkey*AT_STRIDE + dk] = vl;
                }
            }
        }
        __syncthreads();

        // S = Q K^T
        float sc[8][4];
        #pragma unroll
        for (int j = 0; j < 8; j++)
            #pragma unroll
            for (int r = 0; r < 4; r++) sc[j][r] = 0.0f;

        #pragma unroll
        for (int j = 0; j < 8; j++) {
            #pragma unroll
            for (int c = 0; c < 8; c++) {
                int off  = (8*c + tig)*AT_STRIDE + 8*j + gid;
                int off2 = off + 4*AT_STRIDE;
                mma_tf32(sc[j], qf[c], Khi[off], Khi[off2]);
                mma_tf32(sc[j], qf[c], Klo[off], Klo[off2]);
            }
        }

        // Causal mask (diagonal-ish tiles only)
        if (kt*64 + 63 > row0) {
            #pragma unroll
            for (int j = 0; j < 8; j++) {
                int col = kt*64 + 8*j + 2*tig;
                if (col     > row0) sc[j][0] = -1e30f;
                if (col + 1 > row0) sc[j][1] = -1e30f;
                if (col     > row1) sc[j][2] = -1e30f;
                if (col + 1 > row1) sc[j][3] = -1e30f;
            }
        }

        // Online softmax (rows gid / gid+8, spread over the quad)
        float mx0 = -INFINITY, mx1 = -INFINITY;
        #pragma unroll
        for (int j = 0; j < 8; j++) {
            mx0 = fmaxf(mx0, fmaxf(sc[j][0], sc[j][1]));
            mx1 = fmaxf(mx1, fmaxf(sc[j][2], sc[j][3]));
        }
        #pragma unroll
        for (int off = 1; off <= 2; off <<= 1) {
            mx0 = fmaxf(mx0, __shfl_xor_sync(0xffffffffu, mx0, off));
            mx1 = fmaxf(mx1, __shfl_xor_sync(0xffffffffu, mx1, off));
        }
        float mn0 = fmaxf(m0, mx0), mn1 = fmaxf(m1, mx1);
        float a0 = ex2((m0 - mn0)*COEF), a1 = ex2((m1 - mn1)*COEF);
        m0 = mn0; m1 = mn1;

        float ls0 = 0.0f, ls1 = 0.0f;
        uint32_t pt[8][4];
        #pragma unroll
        for (int j = 0; j < 8; j++) {
            float p0 = ex2((sc[j][0] - m0)*COEF);
            float p1 = ex2((sc[j][1] - m0)*COEF);
            float p2 = ex2((sc[j][2] - m1)*COEF);
            float p3 = ex2((sc[j][3] - m1)*COEF);
            ls0 += p0 + p1; ls1 += p2 + p3;
            pt[j][0] = f2tf32(p0); pt[j][1] = f2tf32(p1);
            pt[j][2] = f2tf32(p2); pt[j][3] = f2tf32(p3);
        }
        #pragma unroll
        for (int off = 1; off <= 2; off <<= 1) {
            ls0 += __shfl_xor_sync(0xffffffffu, ls0, off);
            ls1 += __shfl_xor_sync(0xffffffffu, ls1, off);
        }
        l0 = l0*a0 + ls0;
        l1 = l1*a1 + ls1;
        #pragma unroll
        for (int j = 0; j < 8; j++) {
            o[j][0] *= a0; o[j][1] *= a0;
            o[j][2] *= a1; o[j][3] *= a1;
        }

        // O += P V  (repack P accum-layout -> A-fragment via quad shuffles)
        const int srcA = (lane & 28) | (tig >> 1);
        const int srcB = srcA + 2;
        const bool oddc = (tig & 1);
        #pragma unroll
        for (int c = 0; c < 8; c++) {
            uint32_t e0 = __shfl_sync(0xffffffffu, pt[c][0], srcA);
            uint32_t d0 = __shfl_sync(0xffffffffu, pt[c][1], srcA);
            uint32_t e1 = __shfl_sync(0xffffffffu, pt[c][2], srcA);
            uint32_t d1 = __shfl_sync(0xffffffffu, pt[c][3], srcA);
            uint32_t e2 = __shfl_sync(0xffffffffu, pt[c][0], srcB);
            uint32_t d2 = __shfl_sync(0xffffffffu, pt[c][1], srcB);
            uint32_t e3 = __shfl_sync(0xffffffffu, pt[c][2], srcB);
            uint32_t d3 = __shfl_sync(0xffffffffu, pt[c][3], srcB);
            uint32_t af[4];
            af[0] = oddc ? d0 : e0;
            af[1] = oddc ? d1 : e1;
            af[2] = oddc ? d2 : e2;
            af[3] = oddc ? d3 : e3;
            #pragma unroll
            for (int j = 0; j < 8; j++) {
                int off  = (8*c + tig)*AT_STRIDE + 8*j + gid;
                int off2 = off + 4*AT_STRIDE;
                mma_tf32(o[j], af, Vhi[off], Vhi[off2]);
                mma_tf32(o[j], af, Vlo[off], Vlo[off2]);
            }
        }
    }

    // Finalize
    const float inv0 = 1.0f / l0, inv1 = 1.0f / l1;
    const int b = bh >> 4, h = bh & 15;
    float* x0 = X + ((size_t)(b*SQ + row0))*DM + h*DKH;
    float* x1 = X + ((size_t)(b*SQ + row1))*DM + h*DKH;
    #pragma unroll
    for (int j = 0; j < 8; j++) {
        int col = 8*j + 2*tig;
        *(float2*)(x0 + col) = make_float2(o[j][0]*inv0, o[j][1]*inv0);
        *(float2*)(x1 + col) = make_float2(o[j][2]*inv1, o[j][3]*inv1);
    }
}

// ---------------------------------------------------------------------------
// Launch
// ---------------------------------------------------------------------------
extern "C" void kernel_launch(void* const* d_in, const int* in_sizes, int n_in,
                              void* d_out, int out_size)
{
    (void)in_sizes; (void)n_in; (void)out_size;
    const float* q  = (const float*)d_in[0];
    const float* k  = (const float*)d_in[1];
    const float* v  = (const float*)d_in[2];
    const float* Wq = (const float*)d_in[4];
    const float* bq = (const float*)d_in[5];
    const float* Wk = (const float*)d_in[6];
    const float* bk = (const float*)d_in[7];
    const float* Wv = (const float*)d_in[8];
    const float* bv = (const float*)d_in[9];
    const float* Wo = (const float*)d_in[10];
    const float* bo = (const float*)d_in[11];
    float* out = (float*)d_out;

    float *Qp, *Kp, *Vp, *Xp;
    cudaGetSymbolAddress((void**)&Qp, g_Q);
    cudaGetSymbolAddress((void**)&Kp, g_K);
    cudaGetSymbolAddress((void**)&Vp, g_V);
    cudaGetSymbolAddress((void**)&Xp, g_X);

    cudaFuncSetAttribute(gemm_tf32,
                         cudaFuncAttributeMaxDynamicSharedMemorySize, GEMM_SMEM);
    cudaFuncSetAttribute(attn_tc,
                         cudaFuncAttributeMaxDynamicSharedMemorySize, ATTN_SMEM);

    dim3 gg(DM/BN, NTOK/BM);   // (8, 32)
    gemm_tf32<<<gg, 256, GEMM_SMEM>>>(q, Wq, bq, Qp, 1);
    gemm_tf32<<<gg, 256, GEMM_SMEM>>>(k, Wk, bk, Kp, 1);
    gemm_tf32<<<gg, 256, GEMM_SMEM>>>(v, Wv, bv, Vp, 1);
    attn_tc<<<dim3(SQ/128, NB*NH), 256, ATTN_SMEM>>>(Qp, Kp, Vp, Xp);
    gemm_tf32<<<gg, 256, GEMM_SMEM>>>(Xp, Wo, bo, out, 0);
}

// round 5
// speedup vs baseline: 2.5798x; 1.1786x over previous
#include <cuda_runtime.h>
#include <math.h>
#include <cstdint>

// Problem constants
#define SQ    2048
#define DM    1024
#define NH    16
#define DKH   64
#define NB    2
#define NTOK  (NB*SQ)   // 4096

// ---------------------------------------------------------------------------
// Scratch (no cudaMalloc allowed)
// ---------------------------------------------------------------------------
__device__ float g_Q  [(size_t)NB*NH*SQ*DKH];
__device__ float g_Khi[(size_t)NB*NH*SQ*DKH];   // [B,H,dk,S] (transposed)
__device__ float g_Klo[(size_t)NB*NH*SQ*DKH];
__device__ float g_Vhi[(size_t)NB*NH*SQ*DKH];   // [B,H,S,dk]
__device__ float g_Vlo[(size_t)NB*NH*SQ*DKH];
__device__ float g_X  [(size_t)NTOK*DM];

// ---------------------------------------------------------------------------
// Helpers
// ---------------------------------------------------------------------------
__device__ __forceinline__ uint32_t f2tf32(float f) {
    uint32_t r;
    asm("cvt.rna.tf32.f32 %0, %1;" : "=r"(r) : "f"(f));
    return r;
}
__device__ __forceinline__ float tf32hi(float f) {
    return __uint_as_float(f2tf32(f));
}
__device__ __forceinline__ float ex2(float x) {
    float y;
    asm("ex2.approx.f32 %0, %1;" : "=f"(y) : "f"(x));
    return y;
}
__device__ __forceinline__ void mma_tf32(float c[4], const uint32_t a[4],
                                         const uint32_t b0, const uint32_t b1) {
    asm volatile(
        "mma.sync.aligned.m16n8k8.row.col.f32.tf32.tf32.f32 "
        "{%0,%1,%2,%3}, {%4,%5,%6,%7}, {%8,%9}, {%0,%1,%2,%3};"
        : "+f"(c[0]), "+f"(c[1]), "+f"(c[2]), "+f"(c[3])
        : "r"(a[0]), "r"(a[1]), "r"(a[2]), "r"(a[3]),
          "r"(b0), "r"(b1));
}
__device__ __forceinline__ void cp16(uint32_t saddr, const float* g) {
    asm volatile("cp.async.cg.shared.global [%0], [%1], 16;"
                 :: "r"(saddr), "l"(g) : "memory");
}
#define CP_COMMIT() asm volatile("cp.async.commit_group;" ::: "memory")
#define CP_WAIT0()  asm volatile("cp.async.wait_group 0;" ::: "memory")

__device__ __forceinline__ uint32_t smem_u32(const void* p) {
    uint32_t a;
    asm("{ .reg .u64 t; cvta.to.shared.u64 t, %1; cvt.u32.u64 %0, t; }"
        : "=r"(a) : "l"(p));
    return a;
}

// ---------------------------------------------------------------------------
// tf32 mma.sync GEMM: C = A @ W^T + bias
// mode 0: C row-major [M,N]
// mode 1: scatter [B,H,S,DK] (fp32)
// mode 2: K split: hi->C, lo->C2, TRANSPOSED [B,H,dk,S]
// mode 3: V split: hi->C, lo->C2, [B,H,S,dk]
// ---------------------------------------------------------------------------
#define BM 128
#define BN 128
#define BK 32
#define SA 136
#define A_STAGE (BK*SA)
#define GEMM_SMEM (4*A_STAGE*4)
#define GEMM_NT (DM/BK)

__global__ __launch_bounds__(256)
void gemm_tf32(const float* __restrict__ A, const float* __restrict__ W,
               const float* __restrict__ bias, float* __restrict__ C,
               float* __restrict__ C2, int mode)
{
    extern __shared__ uint32_t sh[];
    uint32_t* As = sh;
    uint32_t* Bs = sh + 2*A_STAGE;

    const int tid    = threadIdx.x;
    const int wid    = tid >> 5;
    const int lane   = tid & 31;
    const int gid    = lane >> 2;
    const int tig    = lane & 3;
    const int warp_m = (wid >> 2) * 64;
    const int warp_n = (wid & 3) * 32;
    const int bx     = blockIdx.x;
    const int by     = blockIdx.y;

    const int lrow  = tid >> 1;
    const int lcol0 = (tid & 1) * 16;
    const float* Ag = A + (size_t)(by*BM + lrow)*DM + lcol0;
    const float* Wg = W + (size_t)(bx*BN + lrow)*DM + lcol0;

    float4 fa[4], fw[4];
    auto ldg_tile = [&](int kt) {
        const float* ap = Ag + kt*BK;
        const float* wp = Wg + kt*BK;
        #pragma unroll
        for (int i = 0; i < 4; i++) {
            fa[i] = *(const float4*)(ap + i*4);
            fw[i] = *(const float4*)(wp + i*4);
        }
    };
    auto sts_tile = [&](int stage) {
        uint32_t* a = As + stage*A_STAGE;
        uint32_t* b = Bs + stage*A_STAGE;
        #pragma unroll
        for (int i = 0; i < 4; i++) {
            int k = lcol0 + i*4;
            a[(k+0)*SA + lrow] = f2tf32(fa[i].x);
            a[(k+1)*SA + lrow] = f2tf32(fa[i].y);
            a[(k+2)*SA + lrow] = f2tf32(fa[i].z);
            a[(k+3)*SA + lrow] = f2tf32(fa[i].w);
            b[(k+0)*SA + lrow] = f2tf32(fw[i].x);
            b[(k+1)*SA + lrow] = f2tf32(fw[i].y);
            b[(k+2)*SA + lrow] = f2tf32(fw[i].z);
            b[(k+3)*SA + lrow] = f2tf32(fw[i].w);
        }
    };

    float acc[4][4][4];
    #pragma unroll
    for (int i = 0; i < 4; i++)
        #pragma unroll
        for (int j = 0; j < 4; j++)
            #pragma unroll
            for (int r = 0; r < 4; r++) acc[i][j][r] = 0.0f;

    ldg_tile(0);
    sts_tile(0);
    __syncthreads();

    for (int kt = 0; kt < GEMM_NT; kt++) {
        if (kt + 1 < GEMM_NT) ldg_tile(kt + 1);

        const uint32_t* a = As + (kt & 1)*A_STAGE;
        const uint32_t* b = Bs + (kt & 1)*A_STAGE;
        #pragma unroll
        for (int ks = 0; ks < BK; ks += 8) {
            uint32_t af[4][4], bf[4][2];
            #pragma unroll
            for (int i = 0; i < 4; i++) {
                int r0 = warp_m + i*16 + gid;
                af[i][0] = a[(ks+tig  )*SA + r0];
                af[i][1] = a[(ks+tig  )*SA + r0 + 8];
                af[i][2] = a[(ks+tig+4)*SA + r0];
                af[i][3] = a[(ks+tig+4)*SA + r0 + 8];
            }
            #pragma unroll
            for (int j = 0; j < 4; j++) {
                int n = warp_n + j*8 + gid;
                bf[j][0] = b[(ks+tig  )*SA + n];
                bf[j][1] = b[(ks+tig+4)*SA + n];
            }
            #pragma unroll
            for (int i = 0; i < 4; i++)
                #pragma unroll
                for (int j = 0; j < 4; j++)
                    mma_tf32(acc[i][j], af[i], bf[j][0], bf[j][1]);
        }

        if (kt + 1 < GEMM_NT) sts_tile((kt + 1) & 1);
        __syncthreads();
    }

    #pragma unroll
    for (int i = 0; i < 4; i++) {
        #pragma unroll
        for (int j = 0; j < 4; j++) {
            int row0 = by*BM + warp_m + i*16 + gid;
            int row1 = row0 + 8;
            int col  = bx*BN + warp_n + j*8 + tig*2;
            float bx0 = bias[col], bx1 = bias[col+1];
            float v00 = acc[i][j][0] + bx0, v01 = acc[i][j][1] + bx1;
            float v10 = acc[i][j][2] + bx0, v11 = acc[i][j][3] + bx1;
            if (mode == 0) {
                *(float2*)(C + (size_t)row0*DM + col) = make_float2(v00, v01);
                *(float2*)(C + (size_t)row1*DM + col) = make_float2(v10, v11);
            } else if (mode == 1) {
                int h  = col >> 6, dk = col & (DKH-1);
                int b0 = row0 >> 11, s0 = row0 & (SQ-1);
                int b1 = row1 >> 11, s1 = row1 & (SQ-1);
                *(float2*)(C + (((size_t)(b0*NH + h)*SQ) + s0)*DKH + dk) = make_float2(v00, v01);
                *(float2*)(C + (((size_t)(b1*NH + h)*SQ) + s1)*DKH + dk) = make_float2(v10, v11);
            } else if (mode == 2) {
                // transposed [B,H,dk,S]
                int h  = col >> 6, dk = col & (DKH-1);
                int b0 = row0 >> 11, s0 = row0 & (SQ-1);
                int b1 = row1 >> 11, s1 = row1 & (SQ-1);
                size_t base0 = ((size_t)(b0*NH + h)*DKH + dk)*SQ;
                size_t base1 = ((size_t)(b1*NH + h)*DKH + dk)*SQ;
                float h00 = tf32hi(v00), h01 = tf32hi(v01);
                float h10 = tf32hi(v10), h11 = tf32hi(v11);
                C [base0 + s0]      = h00;
                C [base0 + SQ + s0] = h01;
                C [base1 + s1]      = h10;
                C [base1 + SQ + s1] = h11;
                C2[base0 + s0]      = tf32hi(v00 - h00);
                C2[base0 + SQ + s0] = tf32hi(v01 - h01);
                C2[base1 + s1]      = tf32hi(v10 - h10);
                C2[base1 + SQ + s1] = tf32hi(v11 - h11);
            } else {
                // mode 3: V split, [B,H,S,dk]
                int h  = col >> 6, dk = col & (DKH-1);
                int b0 = row0 >> 11, s0 = row0 & (SQ-1);
                int b1 = row1 >> 11, s1 = row1 & (SQ-1);
                size_t o0 = (((size_t)(b0*NH + h)*SQ) + s0)*DKH + dk;
                size_t o1 = (((size_t)(b1*NH + h)*SQ) + s1)*DKH + dk;
                float h00 = tf32hi(v00), h01 = tf32hi(v01);
                float h10 = tf32hi(v10), h11 = tf32hi(v11);
                *(float2*)(C  + o0) = make_float2(h00, h01);
                *(float2*)(C  + o1) = make_float2(h10, h11);
                *(float2*)(C2 + o0) = make_float2(tf32hi(v00 - h00), tf32hi(v01 - h01));
                *(float2*)(C2 + o1) = make_float2(tf32hi(v10 - h10), tf32hi(v11 - h11));
            }
        }
    }
}

// ---------------------------------------------------------------------------
// Tensor-core causal flash attention, tf32 mma.sync.
// Pre-split K/V loaded via cp.async, double-buffered.
// K: [dk][key] transposed in smem; V: [key][dk]; stride 72 (conflict-free).
// ---------------------------------------------------------------------------
#define AT_STRIDE   72
#define ARR_WORDS   (64*AT_STRIDE)             // 4608
#define STAGE_WORDS (4*ARR_WORDS)              // 18432
#define ATTN_SMEM   (2*STAGE_WORDS*4)          // 147456 B
#define COEF 0.18033688f                       // 0.125 * log2(e)

__global__ __launch_bounds__(256, 1)
void attn_tc(const float* __restrict__ Q,
             const float* __restrict__ Khi, const float* __restrict__ Klo,
             const float* __restrict__ Vhi, const float* __restrict__ Vlo,
             float* __restrict__ X)
{
    extern __shared__ uint32_t sh[];
    const uint32_t smem0 = smem_u32(sh);

    const int qt   = (int)gridDim.x - 1 - (int)blockIdx.x;  // heavy tiles first
    const int bh   = blockIdx.y;
    const int tid  = threadIdx.x;
    const int wid  = tid >> 5;
    const int lane = tid & 31;
    const int gid  = lane >> 2;
    const int tig  = lane & 3;

    const int row0 = qt*128 + wid*16 + gid;
    const int row1 = row0 + 8;

    // Q fragments in registers (tf32)
    uint32_t qf[8][4];
    {
        const float* q0 = Q + ((size_t)bh*SQ + row0)*DKH;
        const float* q1 = Q + ((size_t)bh*SQ + row1)*DKH;
        #pragma unroll
        for (int c = 0; c < 8; c++) {
            qf[c][0] = f2tf32(q0[8*c + tig]);
            qf[c][1] = f2tf32(q1[8*c + tig]);
            qf[c][2] = f2tf32(q0[8*c + tig + 4]);
            qf[c][3] = f2tf32(q1[8*c + tig + 4]);
        }
    }

    float o[8][4];
    #pragma unroll
    for (int j = 0; j < 8; j++)
        #pragma unroll
        for (int r = 0; r < 4; r++) o[j][r] = 0.0f;
    float m0 = -INFINITY, m1 = -INFINITY, l0 = 0.0f, l1 = 0.0f;

    const float* KhiG = Khi + (size_t)bh*DKH*SQ;
    const float* KloG = Klo + (size_t)bh*DKH*SQ;
    const float* VhiG = Vhi + (size_t)bh*SQ*DKH;
    const float* VloG = Vlo + (size_t)bh*SQ*DKH;

    // Prefetch: per thread 4 chunks per array (64 rows x 16 chunks of 16B)
    auto prefetch = [&](int kt, int st) {
        const uint32_t base = smem0 + st*(STAGE_WORDS*4);
        #pragma unroll
        for (int t = 0; t < 4; t++) {
            int idx = tid + t*256;
            int row = idx >> 4;          // 0..63
            int ch  = idx & 15;          // 16B chunk
            uint32_t woff = (uint32_t)(row*AT_STRIDE*4 + ch*16);
            // K arrays: row = dk, 64 keys per row
            cp16(base + woff,                 KhiG + (size_t)row*SQ + kt*64 + ch*4);
            cp16(base + ARR_WORDS*4 + woff,   KloG + (size_t)row*SQ + kt*64 + ch*4);
            // V arrays: row = key, 64 dk per row
            cp16(base + 2*ARR_WORDS*4 + woff, VhiG + (size_t)(kt*64 + row)*DKH + ch*4);
            cp16(base + 3*ARR_WORDS*4 + woff, VloG + (size_t)(kt*64 + row)*DKH + ch*4);
        }
        CP_COMMIT();
    };

    const int ktmax = 2*qt + 1;
    prefetch(0, 0);

    for (int kt = 0; kt <= ktmax; kt++) {
        const int st = kt & 1;
        CP_WAIT0();
        __syncthreads();
        if (kt < ktmax) prefetch(kt + 1, st ^ 1);

        const uint32_t* sKhi = sh + st*STAGE_WORDS;
        const uint32_t* sKlo = sKhi + ARR_WORDS;
        const uint32_t* sVhi = sKhi + 2*ARR_WORDS;
        const uint32_t* sVlo = sKhi + 3*ARR_WORDS;

        // S = Q K^T
        float sc[8][4];
        #pragma unroll
        for (int j = 0; j < 8; j++)
            #pragma unroll
            for (int r = 0; r < 4; r++) sc[j][r] = 0.0f;

        #pragma unroll
        for (int j = 0; j < 8; j++) {
            #pragma unroll
            for (int c = 0; c < 8; c++) {
                int off  = (8*c + tig)*AT_STRIDE + 8*j + gid;
                int off2 = off + 4*AT_STRIDE;
                mma_tf32(sc[j], qf[c], sKhi[off], sKhi[off2]);
                mma_tf32(sc[j], qf[c], sKlo[off], sKlo[off2]);
            }
        }

        // Causal mask
        if (kt*64 + 63 > row0) {
            #pragma unroll
            for (int j = 0; j < 8; j++) {
                int col = kt*64 + 8*j + 2*tig;
                if (col     > row0) sc[j][0] = -1e30f;
                if (col + 1 > row0) sc[j][1] = -1e30f;
                if (col     > row1) sc[j][2] = -1e30f;
                if (col + 1 > row1) sc[j][3] = -1e30f;
            }
        }

        // Online softmax
        float mx0 = -INFINITY, mx1 = -INFINITY;
        #pragma unroll
        for (int j = 0; j < 8; j++) {
            mx0 = fmaxf(mx0, fmaxf(sc[j][0], sc[j][1]));
            mx1 = fmaxf(mx1, fmaxf(sc[j][2], sc[j][3]));
        }
        #pragma unroll
        for (int off = 1; off <= 2; off <<= 1) {
            mx0 = fmaxf(mx0, __shfl_xor_sync(0xffffffffu, mx0, off));
            mx1 = fmaxf(mx1, __shfl_xor_sync(0xffffffffu, mx1, off));
        }
        float mn0 = fmaxf(m0, mx0), mn1 = fmaxf(m1, mx1);
        float a0 = ex2((m0 - mn0)*COEF), a1 = ex2((m1 - mn1)*COEF);
        m0 = mn0; m1 = mn1;

        float ls0 = 0.0f, ls1 = 0.0f;
        uint32_t pt[8][4];
        #pragma unroll
        for (int j = 0; j < 8; j++) {
            float p0 = ex2((sc[j][0] - m0)*COEF);
            float p1 = ex2((sc[j][1] - m0)*COEF);
            float p2 = ex2((sc[j][2] - m1)*COEF);
            float p3 = ex2((sc[j][3] - m1)*COEF);
            ls0 += p0 + p1; ls1 += p2 + p3;
            pt[j][0] = f2tf32(p0); pt[j][1] = f2tf32(p1);
            pt[j][2] = f2tf32(p2); pt[j][3] = f2tf32(p3);
        }
        #pragma unroll
        for (int off = 1; off <= 2; off <<= 1) {
            ls0 += __shfl_xor_sync(0xffffffffu, ls0, off);
            ls1 += __shfl_xor_sync(0xffffffffu, ls1, off);
        }
        l0 = l0*a0 + ls0;
        l1 = l1*a1 + ls1;
        #pragma unroll
        for (int j = 0; j < 8; j++) {
            o[j][0] *= a0; o[j][1] *= a0;
            o[j][2] *= a1; o[j][3] *= a1;
        }

        // O += P V
        const int srcA = (lane & 28) | (tig >> 1);
        const int srcB = srcA + 2;
        const bool oddc = (tig & 1);
        #pragma unroll
        for (int c = 0; c < 8; c++) {
            uint32_t e0 = __shfl_sync(0xffffffffu, pt[c][0], srcA);
            uint32_t d0 = __shfl_sync(0xffffffffu, pt[c][1], srcA);
            uint32_t e1 = __shfl_sync(0xffffffffu, pt[c][2], srcA);
            uint32_t d1 = __shfl_sync(0xffffffffu, pt[c][3], srcA);
            uint32_t e2 = __shfl_sync(0xffffffffu, pt[c][0], srcB);
            uint32_t d2 = __shfl_sync(0xffffffffu, pt[c][1], srcB);
            uint32_t e3 = __shfl_sync(0xffffffffu, pt[c][2], srcB);
            uint32_t d3 = __shfl_sync(0xffffffffu, pt[c][3], srcB);
            uint32_t af[4];
            af[0] = oddc ? d0 : e0;
            af[1] = oddc ? d1 : e1;
            af[2] = oddc ? d2 : e2;
            af[3] = oddc ? d3 : e3;
            #pragma unroll
            for (int j = 0; j < 8; j++) {
                int off  = (8*c + tig)*AT_STRIDE + 8*j + gid;
                int off2 = off + 4*AT_STRIDE;
                mma_tf32(o[j], af, sVhi[off], sVhi[off2]);
                mma_tf32(o[j], af, sVlo[off], sVlo[off2]);
            }
        }
        __syncthreads();
    }

    // Finalize
    const float inv0 = 1.0f / l0, inv1 = 1.0f / l1;
    const int b = bh >> 4, h = bh & 15;
    float* x0 = X + ((size_t)(b*SQ + row0))*DM + h*DKH;
    float* x1 = X + ((size_t)(b*SQ + row1))*DM + h*DKH;
    #pragma unroll
    for (int j = 0; j < 8; j++) {
        int col = 8*j + 2*tig;
        *(float2*)(x0 + col) = make_float2(o[j][0]*inv0, o[j][1]*inv0);
        *(float2*)(x1 + col) = make_float2(o[j][2]*inv1, o[j][3]*inv1);
    }
}

// ---------------------------------------------------------------------------
// Launch
// ---------------------------------------------------------------------------
extern "C" void kernel_launch(void* const* d_in, const int* in_sizes, int n_in,
                              void* d_out, int out_size)
{
    (void)in_sizes; (void)n_in; (void)out_size;
    const float* q  = (const float*)d_in[0];
    const float* k  = (const float*)d_in[1];
    const float* v  = (const float*)d_in[2];
    const float* Wq = (const float*)d_in[4];
    const float* bq = (const float*)d_in[5];
    const float* Wk = (const float*)d_in[6];
    const float* bk = (const float*)d_in[7];
    const float* Wv = (const float*)d_in[8];
    const float* bv = (const float*)d_in[9];
    const float* Wo = (const float*)d_in[10];
    const float* bo = (const float*)d_in[11];
    float* out = (float*)d_out;

    float *Qp, *KhiP, *KloP, *VhiP, *VloP, *Xp;
    cudaGetSymbolAddress((void**)&Qp,   g_Q);
    cudaGetSymbolAddress((void**)&KhiP, g_Khi);
    cudaGetSymbolAddress((void**)&KloP, g_Klo);
    cudaGetSymbolAddress((void**)&VhiP, g_Vhi);
    cudaGetSymbolAddress((void**)&VloP, g_Vlo);
    cudaGetSymbolAddress((void**)&Xp,   g_X);

    cudaFuncSetAttribute(gemm_tf32,
                         cudaFuncAttributeMaxDynamicSharedMemorySize, GEMM_SMEM);
    cudaFuncSetAttribute(attn_tc,
                         cudaFuncAttributeMaxDynamicSharedMemorySize, ATTN_SMEM);

    dim3 gg(DM/BN, NTOK/BM);   // (8, 32)
    gemm_tf32<<<gg, 256, GEMM_SMEM>>>(q, Wq, bq, Qp, nullptr, 1);
    gemm_tf32<<<gg, 256, GEMM_SMEM>>>(k, Wk, bk, KhiP, KloP, 2);
    gemm_tf32<<<gg, 256, GEMM_SMEM>>>(v, Wv, bv, VhiP, VloP, 3);
    attn_tc<<<dim3(SQ/128, NB*NH), 256, ATTN_SMEM>>>(Qp, KhiP, KloP, VhiP, VloP, Xp);
    gemm_tf32<<<gg, 256, GEMM_SMEM>>>(Xp, Wo, bo, out, nullptr, 0);
}

// round 6
// speedup vs baseline: 2.9518x; 1.1442x over previous
#include <cuda_runtime.h>
#include <math.h>
#include <cstdint>

// Problem constants
#define SQ    2048
#define DM    1024
#define NH    16
#define DKH   64
#define NB    2
#define NTOK  (NB*SQ)   // 4096

// ---------------------------------------------------------------------------
// Scratch (no cudaMalloc allowed)
// ---------------------------------------------------------------------------
__device__ float g_Q  [(size_t)NB*NH*SQ*DKH];
__device__ float g_Khi[(size_t)NB*NH*SQ*DKH];   // [B,H,dk,S] (transposed)
__device__ float g_Klo[(size_t)NB*NH*SQ*DKH];
__device__ float g_Vhi[(size_t)NB*NH*SQ*DKH];   // [B,H,S,dk]
__device__ float g_Vlo[(size_t)NB*NH*SQ*DKH];
__device__ float g_X  [(size_t)NTOK*DM];        // attn out, pre-rounded tf32
// pre-rounded inputs / weights
__device__ float g_qc [(size_t)NTOK*DM];
__device__ float g_kc [(size_t)NTOK*DM];
__device__ float g_vc [(size_t)NTOK*DM];
__device__ float g_Wqc[(size_t)DM*DM];
__device__ float g_Wkc[(size_t)DM*DM];
__device__ float g_Wvc[(size_t)DM*DM];
__device__ float g_Woc[(size_t)DM*DM];

// ---------------------------------------------------------------------------
// Helpers
// ---------------------------------------------------------------------------
__device__ __forceinline__ uint32_t f2tf32(float f) {
    uint32_t r;
    asm("cvt.rna.tf32.f32 %0, %1;" : "=r"(r) : "f"(f));
    return r;
}
__device__ __forceinline__ float tf32hi(float f) {
    return __uint_as_float(f2tf32(f));
}
__device__ __forceinline__ float ex2(float x) {
    float y;
    asm("ex2.approx.f32 %0, %1;" : "=f"(y) : "f"(x));
    return y;
}
__device__ __forceinline__ void mma_tf32(float c[4], const uint32_t a[4],
                                         const uint32_t b0, const uint32_t b1) {
    asm volatile(
        "mma.sync.aligned.m16n8k8.row.col.f32.tf32.tf32.f32 "
        "{%0,%1,%2,%3}, {%4,%5,%6,%7}, {%8,%9}, {%0,%1,%2,%3};"
        : "+f"(c[0]), "+f"(c[1]), "+f"(c[2]), "+f"(c[3])
        : "r"(a[0]), "r"(a[1]), "r"(a[2]), "r"(a[3]),
          "r"(b0), "r"(b1));
}
__device__ __forceinline__ void cp16(uint32_t saddr, const float* g) {
    asm volatile("cp.async.cg.shared.global [%0], [%1], 16;"
                 :: "r"(saddr), "l"(g) : "memory");
}
#define CP_COMMIT() asm volatile("cp.async.commit_group;" ::: "memory")

__device__ __forceinline__ uint32_t smem_u32(const void* p) {
    uint32_t a;
    asm("{ .reg .u64 t; cvta.to.shared.u64 t, %1; cvt.u32.u64 %0, t; }"
        : "=r"(a) : "l"(p));
    return a;
}

// ---------------------------------------------------------------------------
// tf32 pre-round pass (element-wise, float4)
// ---------------------------------------------------------------------------
__global__ __launch_bounds__(256)
void cvt_tf32_k(const float4* __restrict__ src, float4* __restrict__ dst, int n4)
{
    int i = blockIdx.x*blockDim.x + threadIdx.x;
    if (i < n4) {
        float4 v = src[i];
        v.x = tf32hi(v.x); v.y = tf32hi(v.y);
        v.z = tf32hi(v.z); v.w = tf32hi(v.w);
        dst[i] = v;
    }
}

// ---------------------------------------------------------------------------
// tf32 mma.sync GEMM, cp.async pipeline. Inputs pre-rounded to tf32 values.
// C = A @ W^T + bias
// mode 0: C row-major [M,N]
// mode 1: scatter [B,H,S,DK] (fp32)
// mode 2: K split: hi->C, lo->C2, TRANSPOSED [B,H,dk,S]
// mode 3: V split: hi->C, lo->C2, [B,H,S,dk]
// smem: A,B row-major [row][k], stride KP=36 words (conflict-free fragments).
// ---------------------------------------------------------------------------
#define BK 32
#define KP 36
#define TILE_WORDS (128*KP)            // 4608
#define STAGE_W    (2*TILE_WORDS)      // 9216
#define GEMM_SMEM  (2*STAGE_W*4)       // 73728 B
#define GEMM_NT    (DM/BK)             // 32

__global__ __launch_bounds__(256, 2)
void gemm_tf32(const float* __restrict__ A, const float* __restrict__ W,
               const float* __restrict__ bias, float* __restrict__ C,
               float* __restrict__ C2, int mode)
{
    extern __shared__ uint32_t sh[];
    const uint32_t smem0 = smem_u32(sh);

    const int tid    = threadIdx.x;
    const int wid    = tid >> 5;
    const int lane   = tid & 31;
    const int gid    = lane >> 2;
    const int tig    = lane & 3;
    const int warp_m = (wid >> 2) * 64;
    const int warp_n = (wid & 3) * 32;
    const int bx     = blockIdx.x;
    const int by     = blockIdx.y;

    const float* Ab = A + (size_t)(by*128)*DM;
    const float* Wb = W + (size_t)(bx*128)*DM;

    auto prefetch = [&](int kt, int st) {
        const uint32_t base = smem0 + st*(STAGE_W*4);
        #pragma unroll
        for (int t = 0; t < 4; t++) {
            int chunk = tid + t*256;        // 0..1023
            int row   = chunk >> 3;         // 0..127
            int kc    = (chunk & 7) * 4;    // 0..28
            uint32_t so = (uint32_t)((row*KP + kc)*4);
            cp16(base + so,                Ab + (size_t)row*DM + kt*BK + kc);
            cp16(base + TILE_WORDS*4 + so, Wb + (size_t)row*DM + kt*BK + kc);
        }
        CP_COMMIT();
    };

    float acc[4][4][4];
    #pragma unroll
    for (int i = 0; i < 4; i++)
        #pragma unroll
        for (int j = 0; j < 4; j++)
            #pragma unroll
            for (int r = 0; r < 4; r++) acc[i][j][r] = 0.0f;

    prefetch(0, 0);

    for (int kt = 0; kt < GEMM_NT; kt++) {
        if (kt + 1 < GEMM_NT) {
            prefetch(kt + 1, (kt + 1) & 1);
            asm volatile("cp.async.wait_group 1;" ::: "memory");
        } else {
            asm volatile("cp.async.wait_group 0;" ::: "memory");
        }
        __syncthreads();

        const uint32_t* a = sh + (kt & 1)*STAGE_W;
        const uint32_t* b = a + TILE_WORDS;

        #pragma unroll
        for (int ks = 0; ks < BK; ks += 8) {
            uint32_t af[4][4], bf[4][2];
            #pragma unroll
            for (int i = 0; i < 4; i++) {
                int r0 = warp_m + i*16 + gid;
                af[i][0] = a[ r0    *KP + ks + tig    ];
                af[i][1] = a[(r0+8) *KP + ks + tig    ];
                af[i][2] = a[ r0    *KP + ks + tig + 4];
                af[i][3] = a[(r0+8) *KP + ks + tig + 4];
            }
            #pragma unroll
            for (int j = 0; j < 4; j++) {
                int n = warp_n + j*8 + gid;
                bf[j][0] = b[n*KP + ks + tig    ];
                bf[j][1] = b[n*KP + ks + tig + 4];
            }
            #pragma unroll
            for (int i = 0; i < 4; i++)
                #pragma unroll
                for (int j = 0; j < 4; j++)
                    mma_tf32(acc[i][j], af[i], bf[j][0], bf[j][1]);
        }
        __syncthreads();
    }

    #pragma unroll
    for (int i = 0; i < 4; i++) {
        #pragma unroll
        for (int j = 0; j < 4; j++) {
            int row0 = by*128 + warp_m + i*16 + gid;
            int row1 = row0 + 8;
            int col  = bx*128 + warp_n + j*8 + tig*2;
            float bx0 = bias[col], bx1 = bias[col+1];
            float v00 = acc[i][j][0] + bx0, v01 = acc[i][j][1] + bx1;
            float v10 = acc[i][j][2] + bx0, v11 = acc[i][j][3] + bx1;
            if (mode == 0) {
                *(float2*)(C + (size_t)row0*DM + col) = make_float2(v00, v01);
                *(float2*)(C + (size_t)row1*DM + col) = make_float2(v10, v11);
            } else if (mode == 1) {
                int h  = col >> 6, dk = col & (DKH-1);
                int b0 = row0 >> 11, s0 = row0 & (SQ-1);
                int b1 = row1 >> 11, s1 = row1 & (SQ-1);
                *(float2*)(C + (((size_t)(b0*NH + h)*SQ) + s0)*DKH + dk) = make_float2(v00, v01);
                *(float2*)(C + (((size_t)(b1*NH + h)*SQ) + s1)*DKH + dk) = make_float2(v10, v11);
            } else if (mode == 2) {
                int h  = col >> 6, dk = col & (DKH-1);
                int b0 = row0 >> 11, s0 = row0 & (SQ-1);
                int b1 = row1 >> 11, s1 = row1 & (SQ-1);
                size_t base0 = ((size_t)(b0*NH + h)*DKH + dk)*SQ;
                size_t base1 = ((size_t)(b1*NH + h)*DKH + dk)*SQ;
                float h00 = tf32hi(v00), h01 = tf32hi(v01);
                float h10 = tf32hi(v10), h11 = tf32hi(v11);
                C [base0 + s0]      = h00;
                C [base0 + SQ + s0] = h01;
                C [base1 + s1]      = h10;
                C [base1 + SQ + s1] = h11;
                C2[base0 + s0]      = tf32hi(v00 - h00);
                C2[base0 + SQ + s0] = tf32hi(v01 - h01);
                C2[base1 + s1]      = tf32hi(v10 - h10);
                C2[base1 + s1 ? base1 + SQ + s1 : base1 + SQ + s1] = tf32hi(v11 - h11);
            } else {
                int h  = col >> 6, dk = col & (DKH-1);
                int b0 = row0 >> 11, s0 = row0 & (SQ-1);
                int b1 = row1 >> 11, s1 = row1 & (SQ-1);
                size_t o0 = (((size_t)(b0*NH + h)*SQ) + s0)*DKH + dk;
                size_t o1 = (((size_t)(b1*NH + h)*SQ) + s1)*DKH + dk;
                float h00 = tf32hi(v00), h01 = tf32hi(v01);
                float h10 = tf32hi(v10), h11 = tf32hi(v11);
                *(float2*)(C  + o0) = make_float2(h00, h01);
                *(float2*)(C  + o1) = make_float2(h10, h11);
                *(float2*)(C2 + o0) = make_float2(tf32hi(v00 - h00), tf32hi(v01 - h01));
                *(float2*)(C2 + o1) = make_float2(tf32hi(v10 - h10), tf32hi(v11 - h11));
            }
        }
    }
}

// ---------------------------------------------------------------------------
// Tensor-core causal flash attention, tf32 mma.sync (unchanged math from R5).
// Pre-split K/V loaded via cp.async, double-buffered.
// ---------------------------------------------------------------------------
#define AT_STRIDE   72
#define ARR_WORDS   (64*AT_STRIDE)
#define STAGE_WORDS (4*ARR_WORDS)
#define ATTN_SMEM   (2*STAGE_WORDS*4)          // 147456 B
#define COEF 0.18033688f                       // 0.125 * log2(e)

__global__ __launch_bounds__(256, 1)
void attn_tc(const float* __restrict__ Q,
             const float* __restrict__ Khi, const float* __restrict__ Klo,
             const float* __restrict__ Vhi, const float* __restrict__ Vlo,
             float* __restrict__ X)
{
    extern __shared__ uint32_t sh[];
    const uint32_t smem0 = smem_u32(sh);

    const int qt   = (int)gridDim.x - 1 - (int)blockIdx.x;
    const int bh   = blockIdx.y;
    const int tid  = threadIdx.x;
    const int wid  = tid >> 5;
    const int lane = tid & 31;
    const int gid  = lane >> 2;
    const int tig  = lane & 3;

    const int row0 = qt*128 + wid*16 + gid;
    const int row1 = row0 + 8;

    uint32_t qf[8][4];
    {
        const float* q0 = Q + ((size_t)bh*SQ + row0)*DKH;
        const float* q1 = Q + ((size_t)bh*SQ + row1)*DKH;
        #pragma unroll
        for (int c = 0; c < 8; c++) {
            qf[c][0] = f2tf32(q0[8*c + tig]);
            qf[c][1] = f2tf32(q1[8*c + tig]);
            qf[c][2] = f2tf32(q0[8*c + tig + 4]);
            qf[c][3] = f2tf32(q1[8*c + tig + 4]);
        }
    }

    float o[8][4];
    #pragma unroll
    for (int j = 0; j < 8; j++)
        #pragma unroll
        for (int r = 0; r < 4; r++) o[j][r] = 0.0f;
    float m0 = -INFINITY, m1 = -INFINITY, l0 = 0.0f, l1 = 0.0f;

    const float* KhiG = Khi + (size_t)bh*DKH*SQ;
    const float* KloG = Klo + (size_t)bh*DKH*SQ;
    const float* VhiG = Vhi + (size_t)bh*SQ*DKH;
    const float* VloG = Vlo + (size_t)bh*SQ*DKH;

    auto prefetch = [&](int kt, int st) {
        const uint32_t base = smem0 + st*(STAGE_WORDS*4);
        #pragma unroll
        for (int t = 0; t < 4; t++) {
            int idx = tid + t*256;
            int row = idx >> 4;
            int ch  = idx & 15;
            uint32_t woff = (uint32_t)(row*AT_STRIDE*4 + ch*16);
            cp16(base + woff,                 KhiG + (size_t)row*SQ + kt*64 + ch*4);
            cp16(base + ARR_WORDS*4 + woff,   KloG + (size_t)row*SQ + kt*64 + ch*4);
            cp16(base + 2*ARR_WORDS*4 + woff, VhiG + (size_t)(kt*64 + row)*DKH + ch*4);
            cp16(base + 3*ARR_WORDS*4 + woff, VloG + (size_t)(kt*64 + row)*DKH + ch*4);
        }
        CP_COMMIT();
    };

    const int ktmax = 2*qt + 1;
    prefetch(0, 0);

    for (int kt = 0; kt <= ktmax; kt++) {
        const int st = kt & 1;
        asm volatile("cp.async.wait_group 0;" ::: "memory");
        __syncthreads();
        if (kt < ktmax) prefetch(kt + 1, st ^ 1);

        const uint32_t* sKhi = sh + st*STAGE_WORDS;
        const uint32_t* sKlo = sKhi + ARR_WORDS;
        const uint32_t* sVhi = sKhi + 2*ARR_WORDS;
        const uint32_t* sVlo = sKhi + 3*ARR_WORDS;

        float sc[8][4];
        #pragma unroll
        for (int j = 0; j < 8; j++)
            #pragma unroll
            for (int r = 0; r < 4; r++) sc[j][r] = 0.0f;

        #pragma unroll
        for (int j = 0; j < 8; j++) {
            #pragma unroll
            for (int c = 0; c < 8; c++) {
                int off  = (8*c + tig)*AT_STRIDE + 8*j + gid;
                int off2 = off + 4*AT_STRIDE;
                mma_tf32(sc[j], qf[c], sKhi[off], sKhi[off2]);
                mma_tf32(sc[j], qf[c], sKlo[off], sKlo[off2]);
            }
        }

        if (kt*64 + 63 > row0) {
            #pragma unroll
            for (int j = 0; j < 8; j++) {
                int col = kt*64 + 8*j + 2*tig;
                if (col     > row0) sc[j][0] = -1e30f;
                if (col + 1 > row0) sc[j][1] = -1e30f;
                if (col     > row1) sc[j][2] = -1e30f;
                if (col + 1 > row1) sc[j][3] = -1e30f;
            }
        }

        float mx0 = -INFINITY, mx1 = -INFINITY;
        #pragma unroll
        for (int j = 0; j < 8; j++) {
            mx0 = fmaxf(mx0, fmaxf(sc[j][0], sc[j][1]));
            mx1 = fmaxf(mx1, fmaxf(sc[j][2], sc[j][3]));
        }
        #pragma unroll
        for (int off = 1; off <= 2; off <<= 1) {
            mx0 = fmaxf(mx0, __shfl_xor_sync(0xffffffffu, mx0, off));
            mx1 = fmaxf(mx1, __shfl_xor_sync(0xffffffffu, mx1, off));
        }
        float mn0 = fmaxf(m0, mx0), mn1 = fmaxf(m1, mx1);
        float a0 = ex2((m0 - mn0)*COEF), a1 = ex2((m1 - mn1)*COEF);
        m0 = mn0; m1 = mn1;

        float ls0 = 0.0f, ls1 = 0.0f;
        uint32_t pt[8][4];
        #pragma unroll
        for (int j = 0; j < 8; j++) {
            float p0 = ex2((sc[j][0] - m0)*COEF);
            float p1 = ex2((sc[j][1] - m0)*COEF);
            float p2 = ex2((sc[j][2] - m1)*COEF);
            float p3 = ex2((sc[j][3] - m1)*COEF);
            ls0 += p0 + p1; ls1 += p2 + p3;
            pt[j][0] = f2tf32(p0); pt[j][1] = f2tf32(p1);
            pt[j][2] = f2tf32(p2); pt[j][3] = f2tf32(p3);
        }
        #pragma unroll
        for (int off = 1; off <= 2; off <<= 1) {
            ls0 += __shfl_xor_sync(0xffffffffu, ls0, off);
            ls1 += __shfl_xor_sync(0xffffffffu, ls1, off);
        }
        l0 = l0*a0 + ls0;
        l1 = l1*a1 + ls1;
        #pragma unroll
        for (int j = 0; j < 8; j++) {
            o[j][0] *= a0; o[j][1] *= a0;
            o[j][2] *= a1; o[j][3] *= a1;
        }

        const int srcA = (lane & 28) | (tig >> 1);
        const int srcB = srcA + 2;
        const bool oddc = (tig & 1);
        #pragma unroll
        for (int c = 0; c < 8; c++) {
            uint32_t e0 = __shfl_sync(0xffffffffu, pt[c][0], srcA);
            uint32_t d0 = __shfl_sync(0xffffffffu, pt[c][1], srcA);
            uint32_t e1 = __shfl_sync(0xffffffffu, pt[c][2], srcA);
            uint32_t d1 = __shfl_sync(0xffffffffu, pt[c][3], srcA);
            uint32_t e2 = __shfl_sync(0xffffffffu, pt[c][0], srcB);
            uint32_t d2 = __shfl_sync(0xffffffffu, pt[c][1], srcB);
            uint32_t e3 = __shfl_sync(0xffffffffu, pt[c][2], srcB);
            uint32_t d3 = __shfl_sync(0xffffffffu, pt[c][3], srcB);
            uint32_t af[4];
            af[0] = oddc ? d0 : e0;
            af[1] = oddc ? d1 : e1;
            af[2] = oddc ? d2 : e2;
            af[3] = oddc ? d3 : e3;
            #pragma unroll
            for (int j = 0; j < 8; j++) {
                int off  = (8*c + tig)*AT_STRIDE + 8*j + gid;
                int off2 = off + 4*AT_STRIDE;
                mma_tf32(o[j], af, sVhi[off], sVhi[off2]);
                mma_tf32(o[j], af, sVlo[off], sVlo[off2]);
            }
        }
        __syncthreads();
    }

    // Finalize: write X pre-rounded to tf32 (feeds the Wo GEMM directly)
    const float inv0 = 1.0f / l0, inv1 = 1.0f / l1;
    const int b = bh >> 4, h = bh & 15;
    float* x0 = X + ((size_t)(b*SQ + row0))*DM + h*DKH;
    float* x1 = X + ((size_t)(b*SQ + row1))*DM + h*DKH;
    #pragma unroll
    for (int j = 0; j < 8; j++) {
        int col = 8*j + 2*tig;
        *(float2*)(x0 + col) = make_float2(tf32hi(o[j][0]*inv0), tf32hi(o[j][1]*inv0));
        *(float2*)(x1 + col) = make_float2(tf32hi(o[j][2]*inv1), tf32hi(o[j][3]*inv1));
    }
}

// ---------------------------------------------------------------------------
// Launch
// ---------------------------------------------------------------------------
extern "C" void kernel_launch(void* const* d_in, const int* in_sizes, int n_in,
                              void* d_out, int out_size)
{
    (void)in_sizes; (void)n_in; (void)out_size;
    const float* q  = (const float*)d_in[0];
    const float* k  = (const float*)d_in[1];
    const float* v  = (const float*)d_in[2];
    const float* Wq = (const float*)d_in[4];
    const float* bq = (const float*)d_in[5];
    const float* Wk = (const float*)d_in[6];
    const float* bk = (const float*)d_in[7];
    const float* Wv = (const float*)d_in[8];
    const float* bv = (const float*)d_in[9];
    const float* Wo = (const float*)d_in[10];
    const float* bo = (const float*)d_in[11];
    float* out = (float*)d_out;

    float *Qp, *KhiP, *KloP, *VhiP, *VloP, *Xp;
    float *qc, *kc, *vc, *Wqc, *Wkc, *Wvc, *Woc;
    cudaGetSymbolAddress((void**)&Qp,   g_Q);
    cudaGetSymbolAddress((void**)&KhiP, g_Khi);
    cudaGetSymbolAddress((void**)&KloP, g_Klo);
    cudaGetSymbolAddress((void**)&VhiP, g_Vhi);
    cudaGetSymbolAddress((void**)&VloP, g_Vlo);
    cudaGetSymbolAddress((void**)&Xp,   g_X);
    cudaGetSymbolAddress((void**)&qc,   g_qc);
    cudaGetSymbolAddress((void**)&kc,   g_kc);
    cudaGetSymbolAddress((void**)&vc,   g_vc);
    cudaGetSymbolAddress((void**)&Wqc,  g_Wqc);
    cudaGetSymbolAddress((void**)&Wkc,  g_Wkc);
    cudaGetSymbolAddress((void**)&Wvc,  g_Wvc);
    cudaGetSymbolAddress((void**)&Woc,  g_Woc);

    cudaFuncSetAttribute(gemm_tf32,
                         cudaFuncAttributeMaxDynamicSharedMemorySize, GEMM_SMEM);
    cudaFuncSetAttribute(attn_tc,
                         cudaFuncAttributeMaxDynamicSharedMemorySize, ATTN_SMEM);

    const int nA4 = NTOK*DM/4;    // 1,048,576
    const int nW4 = DM*DM/4;      // 262,144
    cvt_tf32_k<<<nA4/256, 256>>>((const float4*)q,  (float4*)qc,  nA4);
    cvt_tf32_k<<<nA4/256, 256>>>((const float4*)k,  (float4*)kc,  nA4);
    cvt_tf32_k<<<nA4/256, 256>>>((const float4*)v,  (float4*)vc,  nA4);
    cvt_tf32_k<<<nW4/256, 256>>>((const float4*)Wq, (float4*)Wqc, nW4);
    cvt_tf32_k<<<nW4/256, 256>>>((const float4*)Wk, (float4*)Wkc, nW4);
    cvt_tf32_k<<<nW4/256, 256>>>((const float4*)Wv, (float4*)Wvc, nW4);
    cvt_tf32_k<<<nW4/256, 256>>>((const float4*)Wo, (float4*)Woc, nW4);

    dim3 gg(DM/128, NTOK/128);   // (8, 32)
    gemm_tf32<<<gg, 256, GEMM_SMEM>>>(qc, Wqc, bq, Qp, nullptr, 1);
    gemm_tf32<<<gg, 256, GEMM_SMEM>>>(kc, Wkc, bk, KhiP, KloP, 2);
    gemm_tf32<<<gg, 256, GEMM_SMEM>>>(vc, Wvc, bv, VhiP, VloP, 3);
    attn_tc<<<dim3(SQ/128, NB*NH), 256, ATTN_SMEM>>>(Qp, KhiP, KloP, VhiP, VloP, Xp);
    gemm_tf32<<<gg, 256, GEMM_SMEM>>>(Xp, Woc, bo, out, nullptr, 0);
}

// round 7
// speedup vs baseline: 3.0542x; 1.0347x over previous
#include <cuda_runtime.h>
#include <math.h>
#include <cstdint>

// Problem constants
#define SQ    2048
#define DM    1024
#define NH    16
#define DKH   64
#define NB    2
#define NTOK  (NB*SQ)   // 4096

// ---------------------------------------------------------------------------
// Scratch (no cudaMalloc allowed)
// ---------------------------------------------------------------------------
__device__ float g_Q  [(size_t)NB*NH*SQ*DKH];
__device__ float g_Khi[(size_t)NB*NH*SQ*DKH];   // [B,H,dk,S] (transposed)
__device__ float g_Klo[(size_t)NB*NH*SQ*DKH];
__device__ float g_Vhi[(size_t)NB*NH*SQ*DKH];   // [B,H,S,dk]
__device__ float g_Vlo[(size_t)NB*NH*SQ*DKH];
__device__ float g_X  [(size_t)NTOK*DM];        // attn out, pre-rounded tf32
// pre-rounded inputs / weights
__device__ float g_qc [(size_t)NTOK*DM];
__device__ float g_kc [(size_t)NTOK*DM];
__device__ float g_vc [(size_t)NTOK*DM];
__device__ float g_Wqc[(size_t)DM*DM];
__device__ float g_Wkc[(size_t)DM*DM];
__device__ float g_Wvc[(size_t)DM*DM];
__device__ float g_Woc[(size_t)DM*DM];

// ---------------------------------------------------------------------------
// Helpers
// ---------------------------------------------------------------------------
__device__ __forceinline__ uint32_t f2tf32(float f) {
    uint32_t r;
    asm("cvt.rna.tf32.f32 %0, %1;" : "=r"(r) : "f"(f));
    return r;
}
__device__ __forceinline__ float tf32hi(float f) {
    return __uint_as_float(f2tf32(f));
}
__device__ __forceinline__ float ex2(float x) {
    float y;
    asm("ex2.approx.f32 %0, %1;" : "=f"(y) : "f"(x));
    return y;
}
__device__ __forceinline__ void mma_tf32(float c[4], const uint32_t a[4],
                                         const uint32_t b0, const uint32_t b1) {
    asm volatile(
        "mma.sync.aligned.m16n8k8.row.col.f32.tf32.tf32.f32 "
        "{%0,%1,%2,%3}, {%4,%5,%6,%7}, {%8,%9}, {%0,%1,%2,%3};"
        : "+f"(c[0]), "+f"(c[1]), "+f"(c[2]), "+f"(c[3])
        : "r"(a[0]), "r"(a[1]), "r"(a[2]), "r"(a[3]),
          "r"(b0), "r"(b1));
}
__device__ __forceinline__ void cp16(uint32_t saddr, const float* g) {
    asm volatile("cp.async.cg.shared.global [%0], [%1], 16;"
                 :: "r"(saddr), "l"(g) : "memory");
}
#define CP_COMMIT() asm volatile("cp.async.commit_group;" ::: "memory")

__device__ __forceinline__ uint32_t smem_u32(const void* p) {
    uint32_t a;
    asm("{ .reg .u64 t; cvta.to.shared.u64 t, %1; cvt.u32.u64 %0, t; }"
        : "=r"(a) : "l"(p));
    return a;
}

// ---------------------------------------------------------------------------
// Merged tf32 pre-round pass: 7 arrays in one launch (grid.y = array id)
// ---------------------------------------------------------------------------
struct CvtJobs {
    const float4* src[7];
    float4*       dst[7];
    int           n4[7];
};

__global__ __launch_bounds__(256)
void cvt_tf32_k(CvtJobs jobs)
{
    const int a = blockIdx.y;
    const int i = blockIdx.x*blockDim.x + threadIdx.x;
    if (i < jobs.n4[a]) {
        float4 v = jobs.src[a][i];
        v.x = tf32hi(v.x); v.y = tf32hi(v.y);
        v.z = tf32hi(v.z); v.w = tf32hi(v.w);
        jobs.dst[a][i] = v;
    }
}

// ---------------------------------------------------------------------------
// tf32 mma.sync GEMM, 3-stage cp.async pipeline, merged jobs (grid.z).
// C = A @ W^T + bias. Inputs pre-rounded to tf32 values.
// mode 0: C row-major [M,N]
// mode 1: scatter [B,H,S,DK] (fp32)
// mode 2: K split: hi->C, lo->C2, TRANSPOSED [B,H,dk,S]
// mode 3: V split: hi->C, lo->C2, [B,H,S,dk]
// smem: A,B row-major [row][k], stride KP=36 words (conflict-free fragments).
// ---------------------------------------------------------------------------
#define BK 32
#define KP 36
#define TILE_WORDS (128*KP)            // 4608
#define STAGE_W    (2*TILE_WORDS)      // 9216 words
#define NSTAGE     3
#define GEMM_SMEM  (NSTAGE*STAGE_W*4)  // 110592 B
#define GEMM_NT    (DM/BK)             // 32

struct GemmJobs {
    const float* A[3];
    const float* W[3];
    const float* bias[3];
    float*       C[3];
    float*       C2[3];
    int          mode[3];
};

__global__ __launch_bounds__(256, 2)
void gemm_tf32(GemmJobs jobs)
{
    extern __shared__ uint32_t sh[];
    const uint32_t smem0 = smem_u32(sh);

    const int z = blockIdx.z;
    const float* __restrict__ A    = jobs.A[z];
    const float* __restrict__ W    = jobs.W[z];
    const float* __restrict__ bias = jobs.bias[z];
    float* __restrict__ C  = jobs.C[z];
    float* __restrict__ C2 = jobs.C2[z];
    const int mode = jobs.mode[z];

    const int tid    = threadIdx.x;
    const int wid    = tid >> 5;
    const int lane   = tid & 31;
    const int gid    = lane >> 2;
    const int tig    = lane & 3;
    const int warp_m = (wid >> 2) * 64;
    const int warp_n = (wid & 3) * 32;
    const int bx     = blockIdx.x;
    const int by     = blockIdx.y;

    const float* Ab = A + (size_t)(by*128)*DM;
    const float* Wb = W + (size_t)(bx*128)*DM;

    auto prefetch = [&](int kt) {
        if (kt < GEMM_NT) {
            const int st = kt % NSTAGE;
            const uint32_t base = smem0 + st*(STAGE_W*4);
            #pragma unroll
            for (int t = 0; t < 4; t++) {
                int chunk = tid + t*256;        // 0..1023
                int row   = chunk >> 3;         // 0..127
                int kc    = (chunk & 7) * 4;    // 0..28
                uint32_t so = (uint32_t)((row*KP + kc)*4);
                cp16(base + so,                Ab + (size_t)row*DM + kt*BK + kc);
                cp16(base + TILE_WORDS*4 + so, Wb + (size_t)row*DM + kt*BK + kc);
            }
        }
        CP_COMMIT();   // always commit (uniform group count)
    };

    float acc[4][4][4];
    #pragma unroll
    for (int i = 0; i < 4; i++)
        #pragma unroll
        for (int j = 0; j < 4; j++)
            #pragma unroll
            for (int r = 0; r < 4; r++) acc[i][j][r] = 0.0f;

    prefetch(0);
    prefetch(1);

    for (int kt = 0; kt < GEMM_NT; kt++) {
        // groups in flight: kt, kt+1  ->  wait until only kt+1 pending
        asm volatile("cp.async.wait_group 1;" ::: "memory");
        __syncthreads();
        prefetch(kt + 2);   // writes stage (kt+2)%3; all warps are past compute(kt-1)

        const uint32_t* a = sh + (kt % NSTAGE)*STAGE_W;
        const uint32_t* b = a + TILE_WORDS;

        #pragma unroll
        for (int ks = 0; ks < BK; ks += 8) {
            uint32_t af[4][4], bf[4][2];
            #pragma unroll
            for (int i = 0; i < 4; i++) {
                int r0 = warp_m + i*16 + gid;
                af[i][0] = a[ r0    *KP + ks + tig    ];
                af[i][1] = a[(r0+8) *KP + ks + tig    ];
                af[i][2] = a[ r0    *KP + ks + tig + 4];
                af[i][3] = a[(r0+8) *KP + ks + tig + 4];
            }
            #pragma unroll
            for (int j = 0; j < 4; j++) {
                int n = warp_n + j*8 + gid;
                bf[j][0] = b[n*KP + ks + tig    ];
                bf[j][1] = b[n*KP + ks + tig + 4];
            }
            #pragma unroll
            for (int i = 0; i < 4; i++)
                #pragma unroll
                for (int j = 0; j < 4; j++)
                    mma_tf32(acc[i][j], af[i], bf[j][0], bf[j][1]);
        }
        // no trailing barrier: next iteration's __syncthreads orders the
        // stage overwrite (prefetch is issued after it).
    }

    #pragma unroll
    for (int i = 0; i < 4; i++) {
        #pragma unroll
        for (int j = 0; j < 4; j++) {
            int row0 = by*128 + warp_m + i*16 + gid;
            int row1 = row0 + 8;
            int col  = bx*128 + warp_n + j*8 + tig*2;
            float bx0 = bias[col], bx1 = bias[col+1];
            float v00 = acc[i][j][0] + bx0, v01 = acc[i][j][1] + bx1;
            float v10 = acc[i][j][2] + bx0, v11 = acc[i][j][3] + bx1;
            if (mode == 0) {
                *(float2*)(C + (size_t)row0*DM + col) = make_float2(v00, v01);
                *(float2*)(C + (size_t)row1*DM + col) = make_float2(v10, v11);
            } else if (mode == 1) {
                int h  = col >> 6, dk = col & (DKH-1);
                int b0 = row0 >> 11, s0 = row0 & (SQ-1);
                int b1 = row1 >> 11, s1 = row1 & (SQ-1);
                *(float2*)(C + (((size_t)(b0*NH + h)*SQ) + s0)*DKH + dk) = make_float2(v00, v01);
                *(float2*)(C + (((size_t)(b1*NH + h)*SQ) + s1)*DKH + dk) = make_float2(v10, v11);
            } else if (mode == 2) {
                int h  = col >> 6, dk = col & (DKH-1);
                int b0 = row0 >> 11, s0 = row0 & (SQ-1);
                int b1 = row1 >> 11, s1 = row1 & (SQ-1);
                size_t base0 = ((size_t)(b0*NH + h)*DKH + dk)*SQ;
                size_t base1 = ((size_t)(b1*NH + h)*DKH + dk)*SQ;
                float h00 = tf32hi(v00), h01 = tf32hi(v01);
                float h10 = tf32hi(v10), h11 = tf32hi(v11);
                C [base0 + s0]      = h00;
                C [base0 + SQ + s0] = h01;
                C [base1 + s1]      = h10;
                C [base1 + SQ + s1] = h11;
                C2[base0 + s0]      = tf32hi(v00 - h00);
                C2[base0 + SQ + s0] = tf32hi(v01 - h01);
                C2[base1 + s1]      = tf32hi(v10 - h10);
                C2[base1 + SQ + s1] = tf32hi(v11 - h11);
            } else {
                int h  = col >> 6, dk = col & (DKH-1);
                int b0 = row0 >> 11, s0 = row0 & (SQ-1);
                int b1 = row1 >> 11, s1 = row1 & (SQ-1);
                size_t o0 = (((size_t)(b0*NH + h)*SQ) + s0)*DKH + dk;
                size_t o1 = (((size_t)(b1*NH + h)*SQ) + s1)*DKH + dk;
                float h00 = tf32hi(v00), h01 = tf32hi(v01);
                float h10 = tf32hi(v10), h11 = tf32hi(v11);
                *(float2*)(C  + o0) = make_float2(h00, h01);
                *(float2*)(C  + o1) = make_float2(h10, h11);
                *(float2*)(C2 + o0) = make_float2(tf32hi(v00 - h00), tf32hi(v01 - h01));
                *(float2*)(C2 + o1) = make_float2(tf32hi(v10 - h10), tf32hi(v11 - h11));
            }
        }
    }
}

// ---------------------------------------------------------------------------
// Tensor-core causal flash attention, tf32 mma.sync.
// Pre-split K/V loaded via cp.async, double-buffered.
// ---------------------------------------------------------------------------
#define AT_STRIDE   72
#define ARR_WORDS   (64*AT_STRIDE)
#define STAGE_WORDS (4*ARR_WORDS)
#define ATTN_SMEM   (2*STAGE_WORDS*4)          // 147456 B
#define COEF 0.18033688f                       // 0.125 * log2(e)

__global__ __launch_bounds__(256, 1)
void attn_tc(const float* __restrict__ Q,
             const float* __restrict__ Khi, const float* __restrict__ Klo,
             const float* __restrict__ Vhi, const float* __restrict__ Vlo,
             float* __restrict__ X)
{
    extern __shared__ uint32_t sh[];
    const uint32_t smem0 = smem_u32(sh);

    const int qt   = (int)gridDim.x - 1 - (int)blockIdx.x;
    const int bh   = blockIdx.y;
    const int tid  = threadIdx.x;
    const int wid  = tid >> 5;
    const int lane = tid & 31;
    const int gid  = lane >> 2;
    const int tig  = lane & 3;

    const int row0 = qt*128 + wid*16 + gid;
    const int row1 = row0 + 8;

    uint32_t qf[8][4];
    {
        const float* q0 = Q + ((size_t)bh*SQ + row0)*DKH;
        const float* q1 = Q + ((size_t)bh*SQ + row1)*DKH;
        #pragma unroll
        for (int c = 0; c < 8; c++) {
            qf[c][0] = f2tf32(q0[8*c + tig]);
            qf[c][1] = f2tf32(q1[8*c + tig]);
            qf[c][2] = f2tf32(q0[8*c + tig + 4]);
            qf[c][3] = f2tf32(q1[8*c + tig + 4]);
        }
    }

    float o[8][4];
    #pragma unroll
    for (int j = 0; j < 8; j++)
        #pragma unroll
        for (int r = 0; r < 4; r++) o[j][r] = 0.0f;
    float m0 = -INFINITY, m1 = -INFINITY, l0 = 0.0f, l1 = 0.0f;

    const float* KhiG = Khi + (size_t)bh*DKH*SQ;
    const float* KloG = Klo + (size_t)bh*DKH*SQ;
    const float* VhiG = Vhi + (size_t)bh*SQ*DKH;
    const float* VloG = Vlo + (size_t)bh*SQ*DKH;

    auto prefetch = [&](int kt, int st) {
        const uint32_t base = smem0 + st*(STAGE_WORDS*4);
        #pragma unroll
        for (int t = 0; t < 4; t++) {
            int idx = tid + t*256;
            int row = idx >> 4;
            int ch  = idx & 15;
            uint32_t woff = (uint32_t)(row*AT_STRIDE*4 + ch*16);
            cp16(base + woff,                 KhiG + (size_t)row*SQ + kt*64 + ch*4);
            cp16(base + ARR_WORDS*4 + woff,   KloG + (size_t)row*SQ + kt*64 + ch*4);
            cp16(base + 2*ARR_WORDS*4 + woff, VhiG + (size_t)(kt*64 + row)*DKH + ch*4);
            cp16(base + 3*ARR_WORDS*4 + woff, VloG + (size_t)(kt*64 + row)*DKH + ch*4);
        }
        CP_COMMIT();
    };

    const int ktmax = 2*qt + 1;
    prefetch(0, 0);

    for (int kt = 0; kt <= ktmax; kt++) {
        const int st = kt & 1;
        asm volatile("cp.async.wait_group 0;" ::: "memory");
        __syncthreads();
        if (kt < ktmax) prefetch(kt + 1, st ^ 1);

        const uint32_t* sKhi = sh + st*STAGE_WORDS;
        const uint32_t* sKlo = sKhi + ARR_WORDS;
        const uint32_t* sVhi = sKhi + 2*ARR_WORDS;
        const uint32_t* sVlo = sKhi + 3*ARR_WORDS;

        float sc[8][4];
        #pragma unroll
        for (int j = 0; j < 8; j++)
            #pragma unroll
            for (int r = 0; r < 4; r++) sc[j][r] = 0.0f;

        #pragma unroll
        for (int j = 0; j < 8; j++) {
            #pragma unroll
            for (int c = 0; c < 8; c++) {
                int off  = (8*c + tig)*AT_STRIDE + 8*j + gid;
                int off2 = off + 4*AT_STRIDE;
                mma_tf32(sc[j], qf[c], sKhi[off], sKhi[off2]);
                mma_tf32(sc[j], qf[c], sKlo[off], sKlo[off2]);
            }
        }

        if (kt*64 + 63 > row0) {
            #pragma unroll
            for (int j = 0; j < 8; j++) {
                int col = kt*64 + 8*j + 2*tig;
                if (col     > row0) sc[j][0] = -1e30f;
                if (col + 1 > row0) sc[j][1] = -1e30f;
                if (col     > row1) sc[j][2] = -1e30f;
                if (col + 1 > row1) sc[j][3] = -1e30f;
            }
        }

        float mx0 = -INFINITY, mx1 = -INFINITY;
        #pragma unroll
        for (int j = 0; j < 8; j++) {
            mx0 = fmaxf(mx0, fmaxf(sc[j][0], sc[j][1]));
            mx1 = fmaxf(mx1, fmaxf(sc[j][2], sc[j][3]));
        }
        #pragma unroll
        for (int off = 1; off <= 2; off <<= 1) {
            mx0 = fmaxf(mx0, __shfl_xor_sync(0xffffffffu, mx0, off));
            mx1 = fmaxf(mx1, __shfl_xor_sync(0xffffffffu, mx1, off));
        }
        float mn0 = fmaxf(m0, mx0), mn1 = fmaxf(m1, mx1);
        float a0 = ex2((m0 - mn0)*COEF), a1 = ex2((m1 - mn1)*COEF);
        m0 = mn0; m1 = mn1;

        float ls0 = 0.0f, ls1 = 0.0f;
        uint32_t pt[8][4];
        #pragma unroll
        for (int j = 0; j < 8; j++) {
            float p0 = ex2((sc[j][0] - m0)*COEF);
            float p1 = ex2((sc[j][1] - m0)*COEF);
            float p2 = ex2((sc[j][2] - m1)*COEF);
            float p3 = ex2((sc[j][3] - m1)*COEF);
            ls0 += p0 + p1; ls1 += p2 + p3;
            pt[j][0] = f2tf32(p0); pt[j][1] = f2tf32(p1);
            pt[j][2] = f2tf32(p2); pt[j][3] = f2tf32(p3);
        }
        #pragma unroll
        for (int off = 1; off <= 2; off <<= 1) {
            ls0 += __shfl_xor_sync(0xffffffffu, ls0, off);
            ls1 += __shfl_xor_sync(0xffffffffu, ls1, off);
        }
        l0 = l0*a0 + ls0;
        l1 = l1*a1 + ls1;
        #pragma unroll
        for (int j = 0; j < 8; j++) {
            o[j][0] *= a0; o[j][1] *= a0;
            o[j][2] *= a1; o[j][3] *= a1;
        }

        const int srcA = (lane & 28) | (tig >> 1);
        const int srcB = srcA + 2;
        const bool oddc = (tig & 1);
        #pragma unroll
        for (int c = 0; c < 8; c++) {
            uint32_t e0 = __shfl_sync(0xffffffffu, pt[c][0], srcA);
            uint32_t d0 = __shfl_sync(0xffffffffu, pt[c][1], srcA);
            uint32_t e1 = __shfl_sync(0xffffffffu, pt[c][2], srcA);
            uint32_t d1 = __shfl_sync(0xffffffffu, pt[c][3], srcA);
            uint32_t e2 = __shfl_sync(0xffffffffu, pt[c][0], srcB);
            uint32_t d2 = __shfl_sync(0xffffffffu, pt[c][1], srcB);
            uint32_t e3 = __shfl_sync(0xffffffffu, pt[c][2], srcB);
            uint32_t d3 = __shfl_sync(0xffffffffu, pt[c][3], srcB);
            uint32_t af[4];
            af[0] = oddc ? d0 : e0;
            af[1] = oddc ? d1 : e1;
            af[2] = oddc ? d2 : e2;
            af[3] = oddc ? d3 : e3;
            #pragma unroll
            for (int j = 0; j < 8; j++) {
                int off  = (8*c + tig)*AT_STRIDE + 8*j + gid;
                int off2 = off + 4*AT_STRIDE;
                mma_tf32(o[j], af, sVhi[off], sVhi[off2]);
                mma_tf32(o[j], af, sVlo[off], sVlo[off2]);
            }
        }
        // no trailing barrier: next iteration's __syncthreads orders the
        // stage overwrite (prefetch is issued after it).
    }

    // Finalize: write X pre-rounded to tf32 (feeds the Wo GEMM directly)
    const float inv0 = 1.0f / l0, inv1 = 1.0f / l1;
    const int b = bh >> 4, h = bh & 15;
    float* x0 = X + ((size_t)(b*SQ + row0))*DM + h*DKH;
    float* x1 = X + ((size_t)(b*SQ + row1))*DM + h*DKH;
    #pragma unroll
    for (int j = 0; j < 8; j++) {
        int col = 8*j + 2*tig;
        *(float2*)(x0 + col) = make_float2(tf32hi(o[j][0]*inv0), tf32hi(o[j][1]*inv0));
        *(float2*)(x1 + col) = make_float2(tf32hi(o[j][2]*inv1), tf32hi(o[j][3]*inv1));
    }
}

// ---------------------------------------------------------------------------
// Launch
// ---------------------------------------------------------------------------
extern "C" void kernel_launch(void* const* d_in, const int* in_sizes, int n_in,
                              void* d_out, int out_size)
{
    (void)in_sizes; (void)n_in; (void)out_size;
    const float* q  = (const float*)d_in[0];
    const float* k  = (const float*)d_in[1];
    const float* v  = (const float*)d_in[2];
    const float* Wq = (const float*)d_in[4];
    const float* bq = (const float*)d_in[5];
    const float* Wk = (const float*)d_in[6];
    const float* bk = (const float*)d_in[7];
    const float* Wv = (const float*)d_in[8];
    const float* bv = (const float*)d_in[9];
    const float* Wo = (const float*)d_in[10];
    const float* bo = (const float*)d_in[11];
    float* out = (float*)d_out;

    float *Qp, *KhiP, *KloP, *VhiP, *VloP, *Xp;
    float *qc, *kc, *vc, *Wqc, *Wkc, *Wvc, *Woc;
    cudaGetSymbolAddress((void**)&Qp,   g_Q);
    cudaGetSymbolAddress((void**)&KhiP, g_Khi);
    cudaGetSymbolAddress((void**)&KloP, g_Klo);
    cudaGetSymbolAddress((void**)&VhiP, g_Vhi);
    cudaGetSymbolAddress((void**)&VloP, g_Vlo);
    cudaGetSymbolAddress((void**)&Xp,   g_X);
    cudaGetSymbolAddress((void**)&qc,   g_qc);
    cudaGetSymbolAddress((void**)&kc,   g_kc);
    cudaGetSymbolAddress((void**)&vc,   g_vc);
    cudaGetSymbolAddress((void**)&Wqc,  g_Wqc);
    cudaGetSymbolAddress((void**)&Wkc,  g_Wkc);
    cudaGetSymbolAddress((void**)&Wvc,  g_Wvc);
    cudaGetSymbolAddress((void**)&Woc,  g_Woc);

    cudaFuncSetAttribute(gemm_tf32,
                         cudaFuncAttributeMaxDynamicSharedMemorySize, GEMM_SMEM);
    cudaFuncSetAttribute(attn_tc,
                         cudaFuncAttributeMaxDynamicSharedMemorySize, ATTN_SMEM);

    const int nA4 = NTOK*DM/4;    // 1,048,576
    const int nW4 = DM*DM/4;      // 262,144

    CvtJobs cj;
    cj.src[0] = (const float4*)q;  cj.dst[0] = (float4*)qc;  cj.n4[0] = nA4;
    cj.src[1] = (const float4*)k;  cj.dst[1] = (float4*)kc;  cj.n4[1] = nA4;
    cj.src[2] = (const float4*)v;  cj.dst[2] = (float4*)vc;  cj.n4[2] = nA4;
    cj.src[3] = (const float4*)Wq; cj.dst[3] = (float4*)Wqc; cj.n4[3] = nW4;
    cj.src[4] = (const float4*)Wk; cj.dst[4] = (float4*)Wkc; cj.n4[4] = nW4;
    cj.src[5] = (const float4*)Wv; cj.dst[5] = (float4*)Wvc; cj.n4[5] = nW4;
    cj.src[6] = (const float4*)Wo; cj.dst[6] = (float4*)Woc; cj.n4[6] = nW4;
    cvt_tf32_k<<<dim3(nA4/256, 7), 256>>>(cj);

    GemmJobs gj;
    gj.A[0] = qc; gj.W[0] = Wqc; gj.bias[0] = bq; gj.C[0] = Qp;   gj.C2[0] = nullptr; gj.mode[0] = 1;
    gj.A[1] = kc; gj.W[1] = Wkc; gj.bias[1] = bk; gj.C[1] = KhiP; gj.C2[1] = KloP;    gj.mode[1] = 2;
    gj.A[2] = vc; gj.W[2] = Wvc; gj.bias[2] = bv; gj.C[2] = VhiP; gj.C2[2] = VloP;    gj.mode[2] = 3;
    gemm_tf32<<<dim3(DM/128, NTOK/128, 3), 256, GEMM_SMEM>>>(gj);

    attn_tc<<<dim3(SQ/128, NB*NH), 256, ATTN_SMEM>>>(Qp, KhiP, KloP, VhiP, VloP, Xp);

    GemmJobs go;
    go.A[0] = Xp; go.W[0] = Woc; go.bias[0] = bo; go.C[0] = out; go.C2[0] = nullptr; go.mode[0] = 0;
    go.A[1] = go.A[2] = nullptr; go.W[1] = go.W[2] = nullptr;
    go.bias[1] = go.bias[2] = nullptr; go.C[1] = go.C[2] = nullptr;
    go.C2[1] = go.C2[2] = nullptr; go.mode[1] = go.mode[2] = 0;
    gemm_tf32<<<dim3(DM/128, NTOK/128, 1), 256, GEMM_SMEM>>>(go);
}

// round 8
// speedup vs baseline: 3.5385x; 1.1586x over previous
#include <cuda_runtime.h>
#include <cuda_bf16.h>
#include <math.h>
#include <cstdint>

// Problem constants
#define SQ    2048
#define DM    1024
#define NH    16
#define DKH   64
#define NB    2
#define NTOK  (NB*SQ)   // 4096
#define BH    (NB*NH)   // 32

// ---------------------------------------------------------------------------
// Scratch (no cudaMalloc allowed)
// ---------------------------------------------------------------------------
// bf16 hi/lo packed-pair outputs of the projections
__device__ uint32_t g_Qhi[(size_t)BH*SQ*32];           // [B,H,S,dk-pairs]
__device__ uint32_t g_Qlo[(size_t)BH*SQ*32];
__device__ uint32_t g_Kh [(size_t)BH*SQ*32];           // [B,H,S,dk-pairs]
__device__ uint32_t g_Kl [(size_t)BH*SQ*32];
__device__ unsigned short g_Vh[(size_t)BH*DKH*SQ];     // [B,H,dk,S] bf16
__device__ unsigned short g_Vl[(size_t)BH*DKH*SQ];
__device__ float g_X  [(size_t)NTOK*DM];               // attn out, tf32-prerounded
// pre-rounded fp32(tf32) inputs / weights for the tf32 GEMMs
__device__ float g_qc [(size_t)NTOK*DM];
__device__ float g_kc [(size_t)NTOK*DM];
__device__ float g_vc [(size_t)NTOK*DM];
__device__ float g_Wqc[(size_t)DM*DM];
__device__ float g_Wkc[(size_t)DM*DM];
__device__ float g_Wvc[(size_t)DM*DM];
__device__ float g_Woc[(size_t)DM*DM];

// ---------------------------------------------------------------------------
// Helpers
// ---------------------------------------------------------------------------
__device__ __forceinline__ uint32_t f2tf32(float f) {
    uint32_t r;
    asm("cvt.rna.tf32.f32 %0, %1;" : "=r"(r) : "f"(f));
    return r;
}
__device__ __forceinline__ float tf32hi(float f) {
    return __uint_as_float(f2tf32(f));
}
__device__ __forceinline__ float ex2(float x) {
    float y;
    asm("ex2.approx.f32 %0, %1;" : "=f"(y) : "f"(x));
    return y;
}
// pack two floats as bf16x2: low half = e (even idx), high half = o (odd idx)
__device__ __forceinline__ uint32_t pack_bf16(float e, float o) {
    uint32_t r;
    asm("cvt.rn.bf16x2.f32 %0, %1, %2;" : "=r"(r) : "f"(o), "f"(e));
    return r;
}
__device__ __forceinline__ float blo_f(uint32_t p) { return __uint_as_float(p << 16); }
__device__ __forceinline__ float bhi_f(uint32_t p) { return __uint_as_float(p & 0xffff0000u); }

__device__ __forceinline__ void mma_tf32(float c[4], const uint32_t a[4],
                                         const uint32_t b0, const uint32_t b1) {
    asm volatile(
        "mma.sync.aligned.m16n8k8.row.col.f32.tf32.tf32.f32 "
        "{%0,%1,%2,%3}, {%4,%5,%6,%7}, {%8,%9}, {%0,%1,%2,%3};"
        : "+f"(c[0]), "+f"(c[1]), "+f"(c[2]), "+f"(c[3])
        : "r"(a[0]), "r"(a[1]), "r"(a[2]), "r"(a[3]),
          "r"(b0), "r"(b1));
}
__device__ __forceinline__ void mma_bf16(float c[4], const uint32_t a[4],
                                         const uint32_t b0, const uint32_t b1) {
    asm volatile(
        "mma.sync.aligned.m16n8k16.row.col.f32.bf16.bf16.f32 "
        "{%0,%1,%2,%3}, {%4,%5,%6,%7}, {%8,%9}, {%0,%1,%2,%3};"
        : "+f"(c[0]), "+f"(c[1]), "+f"(c[2]), "+f"(c[3])
        : "r"(a[0]), "r"(a[1]), "r"(a[2]), "r"(a[3]),
          "r"(b0), "r"(b1));
}
__device__ __forceinline__ void cp16(uint32_t saddr, const void* g) {
    asm volatile("cp.async.cg.shared.global [%0], [%1], 16;"
                 :: "r"(saddr), "l"(g) : "memory");
}
#define CP_COMMIT() asm volatile("cp.async.commit_group;" ::: "memory")

__device__ __forceinline__ uint32_t smem_u32(const void* p) {
    uint32_t a;
    asm("{ .reg .u64 t; cvta.to.shared.u64 t, %1; cvt.u32.u64 %0, t; }"
        : "=r"(a) : "l"(p));
    return a;
}

// ---------------------------------------------------------------------------
// Merged tf32 pre-round pass
// ---------------------------------------------------------------------------
struct CvtJobs {
    const float4* src[7];
    float4*       dst[7];
    int           n4[7];
};

__global__ __launch_bounds__(256)
void cvt_tf32_k(CvtJobs jobs)
{
    const int a = blockIdx.y;
    const int i = blockIdx.x*blockDim.x + threadIdx.x;
    if (i < jobs.n4[a]) {
        float4 v = jobs.src[a][i];
        v.x = tf32hi(v.x); v.y = tf32hi(v.y);
        v.z = tf32hi(v.z); v.w = tf32hi(v.w);
        jobs.dst[a][i] = v;
    }
}

// ---------------------------------------------------------------------------
// tf32 mma.sync GEMM, 3-stage cp.async pipeline, merged jobs (grid.z).
// C = A @ W^T + bias. Inputs pre-rounded to tf32 values.
// mode 0: C row-major fp32 [M,N]
// mode 1: bf16 hi/lo packed dk-pairs -> C,C2 as u32 [B,H,S,32]   (Q and K)
// mode 3: bf16 hi/lo scalar, TRANSPOSED [B,H,dk,S] -> C,C2 as u16 (V)
// ---------------------------------------------------------------------------
#define BK 32
#define KP 36
#define TILE_WORDS (128*KP)
#define STAGE_W    (2*TILE_WORDS)
#define NSTAGE     3
#define GEMM_SMEM  (NSTAGE*STAGE_W*4)
#define GEMM_NT    (DM/BK)

struct GemmJobs {
    const float* A[3];
    const float* W[3];
    const float* bias[3];
    void*        C[3];
    void*        C2[3];
    int          mode[3];
};

__global__ __launch_bounds__(256, 2)
void gemm_tf32(GemmJobs jobs)
{
    extern __shared__ uint32_t sh[];
    const uint32_t smem0 = smem_u32(sh);

    const int z = blockIdx.z;
    const float* __restrict__ A    = jobs.A[z];
    const float* __restrict__ W    = jobs.W[z];
    const float* __restrict__ bias = jobs.bias[z];
    void* C  = jobs.C[z];
    void* C2 = jobs.C2[z];
    const int mode = jobs.mode[z];

    const int tid    = threadIdx.x;
    const int wid    = tid >> 5;
    const int lane   = tid & 31;
    const int gid    = lane >> 2;
    const int tig    = lane & 3;
    const int warp_m = (wid >> 2) * 64;
    const int warp_n = (wid & 3) * 32;
    const int bx     = blockIdx.x;
    const int by     = blockIdx.y;

    const float* Ab = A + (size_t)(by*128)*DM;
    const float* Wb = W + (size_t)(bx*128)*DM;

    auto prefetch = [&](int kt) {
        if (kt < GEMM_NT) {
            const int st = kt % NSTAGE;
            const uint32_t base = smem0 + st*(STAGE_W*4);
            #pragma unroll
            for (int t = 0; t < 4; t++) {
                int chunk = tid + t*256;
                int row   = chunk >> 3;
                int kc    = (chunk & 7) * 4;
                uint32_t so = (uint32_t)((row*KP + kc)*4);
                cp16(base + so,                Ab + (size_t)row*DM + kt*BK + kc);
                cp16(base + TILE_WORDS*4 + so, Wb + (size_t)row*DM + kt*BK + kc);
            }
        }
        CP_COMMIT();
    };

    float acc[4][4][4];
    #pragma unroll
    for (int i = 0; i < 4; i++)
        #pragma unroll
        for (int j = 0; j < 4; j++)
            #pragma unroll
            for (int r = 0; r < 4; r++) acc[i][j][r] = 0.0f;

    prefetch(0);
    prefetch(1);

    for (int kt = 0; kt < GEMM_NT; kt++) {
        asm volatile("cp.async.wait_group 1;" ::: "memory");
        __syncthreads();
        prefetch(kt + 2);

        const uint32_t* a = sh + (kt % NSTAGE)*STAGE_W;
        const uint32_t* b = a + TILE_WORDS;

        #pragma unroll
        for (int ks = 0; ks < BK; ks += 8) {
            uint32_t af[4][4], bf[4][2];
            #pragma unroll
            for (int i = 0; i < 4; i++) {
                int r0 = warp_m + i*16 + gid;
                af[i][0] = a[ r0    *KP + ks + tig    ];
                af[i][1] = a[(r0+8) *KP + ks + tig    ];
                af[i][2] = a[ r0    *KP + ks + tig + 4];
                af[i][3] = a[(r0+8) *KP + ks + tig + 4];
            }
            #pragma unroll
            for (int j = 0; j < 4; j++) {
                int n = warp_n + j*8 + gid;
                bf[j][0] = b[n*KP + ks + tig    ];
                bf[j][1] = b[n*KP + ks + tig + 4];
            }
            #pragma unroll
            for (int i = 0; i < 4; i++)
                #pragma unroll
                for (int j = 0; j < 4; j++)
                    mma_tf32(acc[i][j], af[i], bf[j][0], bf[j][1]);
        }
    }

    #pragma unroll
    for (int i = 0; i < 4; i++) {
        #pragma unroll
        for (int j = 0; j < 4; j++) {
            int row0 = by*128 + warp_m + i*16 + gid;
            int row1 = row0 + 8;
            int col  = bx*128 + warp_n + j*8 + tig*2;
            float bx0 = bias[col], bx1 = bias[col+1];
            float v00 = acc[i][j][0] + bx0, v01 = acc[i][j][1] + bx1;
            float v10 = acc[i][j][2] + bx0, v11 = acc[i][j][3] + bx1;
            if (mode == 0) {
                float* Cf = (float*)C;
                *(float2*)(Cf + (size_t)row0*DM + col) = make_float2(v00, v01);
                *(float2*)(Cf + (size_t)row1*DM + col) = make_float2(v10, v11);
            } else if (mode == 1) {
                // Q/K: bf16 hi/lo packed dk-pairs [B,H,S,32]
                int h = col >> 6, dkp = (col & 63) >> 1;
                int b0r = row0 >> 11, s0 = row0 & (SQ-1);
                int b1r = row1 >> 11, s1 = row1 & (SQ-1);
                size_t o0 = ((size_t)(b0r*NH + h)*SQ + s0)*32 + dkp;
                size_t o1 = ((size_t)(b1r*NH + h)*SQ + s1)*32 + dkp;
                uint32_t h0 = pack_bf16(v00, v01);
                uint32_t h1 = pack_bf16(v10, v11);
                ((uint32_t*)C)[o0] = h0;
                ((uint32_t*)C)[o1] = h1;
                ((uint32_t*)C2)[o0] = pack_bf16(v00 - blo_f(h0), v01 - bhi_f(h0));
                ((uint32_t*)C2)[o1] = pack_bf16(v10 - blo_f(h1), v11 - bhi_f(h1));
            } else {
                // V: bf16 hi/lo scalar, transposed [B,H,dk,S]
                int h = col >> 6, dk = col & 63;
                int b0r = row0 >> 11, s0 = row0 & (SQ-1);
                int b1r = row1 >> 11, s1 = row1 & (SQ-1);
                size_t base00 = ((size_t)(b0r*NH + h)*DKH + dk)*SQ + s0;
                size_t base10 = ((size_t)(b1r*NH + h)*DKH + dk)*SQ + s1;
                uint32_t h0 = pack_bf16(v00, v01);
                uint32_t h1 = pack_bf16(v10, v11);
                uint32_t l0 = pack_bf16(v00 - blo_f(h0), v01 - bhi_f(h0));
                uint32_t l1 = pack_bf16(v10 - blo_f(h1), v11 - bhi_f(h1));
                unsigned short* Ch = (unsigned short*)C;
                unsigned short* Cl = (unsigned short*)C2;
                Ch[base00]      = (unsigned short)(h0 & 0xffff);
                Ch[base00 + SQ] = (unsigned short)(h0 >> 16);
                Ch[base10]      = (unsigned short)(h1 & 0xffff);
                Ch[base10 + SQ] = (unsigned short)(h1 >> 16);
                Cl[base00]      = (unsigned short)(l0 & 0xffff);
                Cl[base00 + SQ] = (unsigned short)(l0 >> 16);
                Cl[base10]      = (unsigned short)(l1 & 0xffff);
                Cl[base10 + SQ] = (unsigned short)(l1 >> 16);
            }
        }
    }
}

// ---------------------------------------------------------------------------
// bf16 tensor-core causal flash attention (3-term compensated splits).
// K smem: [key][dk-pair u32]  (B operand of QK^T, k = dk)
// V smem: [dk][key-pair u32]  (B operand of PV,  k = key)
// stride 36 u32 per row -> conflict-free fragment LDS.
// P repack: accumulator pairs ARE the k16 A-fragment pairs (no shuffles).
// ---------------------------------------------------------------------------
#define AT_RS       36                        // row stride (u32)
#define ARR_W       (64*AT_RS)                // 2304 u32 per array
#define STAGE_WORDS (4*ARR_W)                 // 9216 u32
#define ATTN_SMEM   (2*STAGE_WORDS*4)         // 73728 B
#define COEF 0.18033688f                      // 0.125 * log2(e)

__global__ __launch_bounds__(256, 1)
void attn_tc(const uint32_t* __restrict__ Qhi, const uint32_t* __restrict__ Qlo,
             const uint32_t* __restrict__ Khi, const uint32_t* __restrict__ Klo,
             const unsigned short* __restrict__ Vhi,
             const unsigned short* __restrict__ Vlo,
             float* __restrict__ X)
{
    extern __shared__ uint32_t sh[];
    const uint32_t smem0 = smem_u32(sh);

    const int qt   = (int)gridDim.x - 1 - (int)blockIdx.x;  // heavy tiles first
    const int bh   = blockIdx.y;
    const int tid  = threadIdx.x;
    const int wid  = tid >> 5;
    const int lane = tid & 31;
    const int gid  = lane >> 2;
    const int tig  = lane & 3;

    const int row0 = qt*128 + wid*16 + gid;
    const int row1 = row0 + 8;

    // Q fragments (pre-split bf16 pairs) in registers
    uint32_t qh[4][4], ql[4][4];
    {
        const uint32_t* q0h = Qhi + ((size_t)bh*SQ + row0)*32;
        const uint32_t* q1h = Qhi + ((size_t)bh*SQ + row1)*32;
        const uint32_t* q0l = Qlo + ((size_t)bh*SQ + row0)*32;
        const uint32_t* q1l = Qlo + ((size_t)bh*SQ + row1)*32;
        #pragma unroll
        for (int t = 0; t < 4; t++) {
            qh[t][0] = q0h[8*t + tig];     qh[t][1] = q1h[8*t + tig];
            qh[t][2] = q0h[8*t + tig + 4]; qh[t][3] = q1h[8*t + tig + 4];
            ql[t][0] = q0l[8*t + tig];     ql[t][1] = q1l[8*t + tig];
            ql[t][2] = q0l[8*t + tig + 4]; ql[t][3] = q1l[8*t + tig + 4];
        }
    }

    float o[8][4];
    #pragma unroll
    for (int j = 0; j < 8; j++)
        #pragma unroll
        for (int r = 0; r < 4; r++) o[j][r] = 0.0f;
    float m0 = -INFINITY, m1 = -INFINITY, l0 = 0.0f, l1 = 0.0f;

    const uint32_t*       KhiG = Khi + (size_t)bh*SQ*32;
    const uint32_t*       KloG = Klo + (size_t)bh*SQ*32;
    const unsigned short* VhiG = Vhi + (size_t)bh*DKH*SQ;
    const unsigned short* VloG = Vlo + (size_t)bh*DKH*SQ;

    auto prefetch = [&](int kt, int st) {
        const uint32_t base = smem0 + st*(STAGE_WORDS*4);
        const int rb = tid >> 3;       // 0..31
        const int ch = tid & 7;        // 16B chunk within row
        #pragma unroll
        for (int t = 0; t < 8; t++) {
            const int a = t >> 1;
            const int r = rb + (t & 1)*32;
            const uint32_t saddr = base + (uint32_t)(a*ARR_W*4 + (r*AT_RS + ch*4)*4);
            const void* src;
            if      (a == 0) src = KhiG + (size_t)(kt*64 + r)*32 + ch*4;
            else if (a == 1) src = KloG + (size_t)(kt*64 + r)*32 + ch*4;
            else if (a == 2) src = VhiG + (size_t)r*SQ + kt*64 + ch*8;
            else             src = VloG + (size_t)r*SQ + kt*64 + ch*8;
            cp16(saddr, src);
        }
        CP_COMMIT();
    };

    const int ktmax = 2*qt + 1;
    prefetch(0, 0);

    for (int kt = 0; kt <= ktmax; kt++) {
        const int st = kt & 1;
        asm volatile("cp.async.wait_group 0;" ::: "memory");
        __syncthreads();
        if (kt < ktmax) prefetch(kt + 1, st ^ 1);

        const uint32_t* sKhi = sh + st*STAGE_WORDS;
        const uint32_t* sKlo = sKhi + ARR_W;
        const uint32_t* sVhi = sKhi + 2*ARR_W;
        const uint32_t* sVlo = sKhi + 3*ARR_W;

        // S = Q K^T  (3-term bf16)
        float sc[8][4];
        #pragma unroll
        for (int j = 0; j < 8; j++)
            #pragma unroll
            for (int r = 0; r < 4; r++) sc[j][r] = 0.0f;

        #pragma unroll
        for (int j = 0; j < 8; j++) {
            const int nrow = (8*j + gid)*AT_RS;
            #pragma unroll
            for (int t = 0; t < 4; t++) {
                uint32_t kh0 = sKhi[nrow + 8*t + tig];
                uint32_t kh1 = sKhi[nrow + 8*t + tig + 4];
                uint32_t kl0 = sKlo[nrow + 8*t + tig];
                uint32_t kl1 = sKlo[nrow + 8*t + tig + 4];
                mma_bf16(sc[j], qh[t], kh0, kh1);
                mma_bf16(sc[j], qh[t], kl0, kl1);
                mma_bf16(sc[j], ql[t], kh0, kh1);
            }
        }

        // Causal mask
        if (kt*64 + 63 > row0) {
            #pragma unroll
            for (int j = 0; j < 8; j++) {
                int col = kt*64 + 8*j + 2*tig;
                if (col     > row0) sc[j][0] = -1e30f;
                if (col + 1 > row0) sc[j][1] = -1e30f;
                if (col     > row1) sc[j][2] = -1e30f;
                if (col + 1 > row1) sc[j][3] = -1e30f;
            }
        }

        // Online softmax
        float mx0 = -INFINITY, mx1 = -INFINITY;
        #pragma unroll
        for (int j = 0; j < 8; j++) {
            mx0 = fmaxf(mx0, fmaxf(sc[j][0], sc[j][1]));
            mx1 = fmaxf(mx1, fmaxf(sc[j][2], sc[j][3]));
        }
        #pragma unroll
        for (int off = 1; off <= 2; off <<= 1) {
            mx0 = fmaxf(mx0, __shfl_xor_sync(0xffffffffu, mx0, off));
            mx1 = fmaxf(mx1, __shfl_xor_sync(0xffffffffu, mx1, off));
        }
        float mn0 = fmaxf(m0, mx0), mn1 = fmaxf(m1, mx1);
        float a0 = ex2((m0 - mn0)*COEF), a1 = ex2((m1 - mn1)*COEF);
        m0 = mn0; m1 = mn1;

        float ls0 = 0.0f, ls1 = 0.0f;
        #pragma unroll
        for (int j = 0; j < 8; j++) {
            sc[j][0] = ex2((sc[j][0] - m0)*COEF);
            sc[j][1] = ex2((sc[j][1] - m0)*COEF);
            sc[j][2] = ex2((sc[j][2] - m1)*COEF);
            sc[j][3] = ex2((sc[j][3] - m1)*COEF);
            ls0 += sc[j][0] + sc[j][1];
            ls1 += sc[j][2] + sc[j][3];
        }
        #pragma unroll
        for (int off = 1; off <= 2; off <<= 1) {
            ls0 += __shfl_xor_sync(0xffffffffu, ls0, off);
            ls1 += __shfl_xor_sync(0xffffffffu, ls1, off);
        }
        l0 = l0*a0 + ls0;
        l1 = l1*a1 + ls1;
        #pragma unroll
        for (int j = 0; j < 8; j++) {
            o[j][0] *= a0; o[j][1] *= a0;
            o[j][2] *= a1; o[j][3] *= a1;
        }

        // P: accumulator pairs -> k16 A fragments via bf16x2 packing (no shfl)
        uint32_t ph[4][4], pl[4][4];
        #pragma unroll
        for (int t = 0; t < 4; t++) {
            uint32_t h;
            h = pack_bf16(sc[2*t][0],   sc[2*t][1]);
            ph[t][0] = h;
            pl[t][0] = pack_bf16(sc[2*t][0]   - blo_f(h), sc[2*t][1]   - bhi_f(h));
            h = pack_bf16(sc[2*t][2],   sc[2*t][3]);
            ph[t][1] = h;
            pl[t][1] = pack_bf16(sc[2*t][2]   - blo_f(h), sc[2*t][3]   - bhi_f(h));
            h = pack_bf16(sc[2*t+1][0], sc[2*t+1][1]);
            ph[t][2] = h;
            pl[t][2] = pack_bf16(sc[2*t+1][0] - blo_f(h), sc[2*t+1][1] - bhi_f(h));
            h = pack_bf16(sc[2*t+1][2], sc[2*t+1][3]);
            ph[t][3] = h;
            pl[t][3] = pack_bf16(sc[2*t+1][2] - blo_f(h), sc[2*t+1][3] - bhi_f(h));
        }

        // O += P V  (3-term bf16)
        #pragma unroll
        for (int j = 0; j < 8; j++) {
            const int nrow = (8*j + gid)*AT_RS;
            #pragma unroll
            for (int t = 0; t < 4; t++) {
                uint32_t vh0 = sVhi[nrow + 8*t + tig];
                uint32_t vh1 = sVhi[nrow + 8*t + tig + 4];
                uint32_t vl0 = sVlo[nrow + 8*t + tig];
                uint32_t vl1 = sVlo[nrow + 8*t + tig + 4];
                mma_bf16(o[j], ph[t], vh0, vh1);
                mma_bf16(o[j], ph[t], vl0, vl1);
                mma_bf16(o[j], pl[t], vh0, vh1);
            }
        }
    }

    // Finalize: write X pre-rounded to tf32 (feeds the Wo GEMM)
    const float inv0 = 1.0f / l0, inv1 = 1.0f / l1;
    const int b = bh >> 4, h = bh & 15;
    float* x0 = X + ((size_t)(b*SQ + row0))*DM + h*DKH;
    float* x1 = X + ((size_t)(b*SQ + row1))*DM + h*DKH;
    #pragma unroll
    for (int j = 0; j < 8; j++) {
        int col = 8*j + 2*tig;
        *(float2*)(x0 + col) = make_float2(tf32hi(o[j][0]*inv0), tf32hi(o[j][1]*inv0));
        *(float2*)(x1 + col) = make_float2(tf32hi(o[j][2]*inv1), tf32hi(o[j][3]*inv1));
    }
}

// ---------------------------------------------------------------------------
// Launch
// ---------------------------------------------------------------------------
extern "C" void kernel_launch(void* const* d_in, const int* in_sizes, int n_in,
                              void* d_out, int out_size)
{
    (void)in_sizes; (void)n_in; (void)out_size;
    const float* q  = (const float*)d_in[0];
    const float* k  = (const float*)d_in[1];
    const float* v  = (const float*)d_in[2];
    const float* Wq = (const float*)d_in[4];
    const float* bq = (const float*)d_in[5];
    const float* Wk = (const float*)d_in[6];
    const float* bk = (const float*)d_in[7];
    const float* Wv = (const float*)d_in[8];
    const float* bv = (const float*)d_in[9];
    const float* Wo = (const float*)d_in[10];
    const float* bo = (const float*)d_in[11];
    float* out = (float*)d_out;

    uint32_t *QhiP, *QloP, *KhP, *KlP;
    unsigned short *VhP, *VlP;
    float *Xp, *qc, *kc, *vc, *Wqc, *Wkc, *Wvc, *Woc;
    cudaGetSymbolAddress((void**)&QhiP, g_Qhi);
    cudaGetSymbolAddress((void**)&QloP, g_Qlo);
    cudaGetSymbolAddress((void**)&KhP,  g_Kh);
    cudaGetSymbolAddress((void**)&KlP,  g_Kl);
    cudaGetSymbolAddress((void**)&VhP,  g_Vh);
    cudaGetSymbolAddress((void**)&VlP,  g_Vl);
    cudaGetSymbolAddress((void**)&Xp,   g_X);
    cudaGetSymbolAddress((void**)&qc,   g_qc);
    cudaGetSymbolAddress((void**)&kc,   g_kc);
    cudaGetSymbolAddress((void**)&vc,   g_vc);
    cudaGetSymbolAddress((void**)&Wqc,  g_Wqc);
    cudaGetSymbolAddress((void**)&Wkc,  g_Wkc);
    cudaGetSymbolAddress((void**)&Wvc,  g_Wvc);
    cudaGetSymbolAddress((void**)&Woc,  g_Woc);

    cudaFuncSetAttribute(gemm_tf32,
                         cudaFuncAttributeMaxDynamicSharedMemorySize, GEMM_SMEM);
    cudaFuncSetAttribute(attn_tc,
                         cudaFuncAttributeMaxDynamicSharedMemorySize, ATTN_SMEM);

    const int nA4 = NTOK*DM/4;
    const int nW4 = DM*DM/4;

    CvtJobs cj;
    cj.src[0] = (const float4*)q;  cj.dst[0] = (float4*)qc;  cj.n4[0] = nA4;
    cj.src[1] = (const float4*)k;  cj.dst[1] = (float4*)kc;  cj.n4[1] = nA4;
    cj.src[2] = (const float4*)v;  cj.dst[2] = (float4*)vc;  cj.n4[2] = nA4;
    cj.src[3] = (const float4*)Wq; cj.dst[3] = (float4*)Wqc; cj.n4[3] = nW4;
    cj.src[4] = (const float4*)Wk; cj.dst[4] = (float4*)Wkc; cj.n4[4] = nW4;
    cj.src[5] = (const float4*)Wv; cj.dst[5] = (float4*)Wvc; cj.n4[5] = nW4;
    cj.src[6] = (const float4*)Wo; cj.dst[6] = (float4*)Woc; cj.n4[6] = nW4;
    cvt_tf32_k<<<dim3(nA4/256, 7), 256>>>(cj);

    GemmJobs gj;
    gj.A[0] = qc; gj.W[0] = Wqc; gj.bias[0] = bq; gj.C[0] = QhiP; gj.C2[0] = QloP; gj.mode[0] = 1;
    gj.A[1] = kc; gj.W[1] = Wkc; gj.bias[1] = bk; gj.C[1] = KhP;  gj.C2[1] = KlP;  gj.mode[1] = 1;
    gj.A[2] = vc; gj.W[2] = Wvc; gj.bias[2] = bv; gj.C[2] = VhP;  gj.C2[2] = VlP;  gj.mode[2] = 3;
    gemm_tf32<<<dim3(DM/128, NTOK/128, 3), 256, GEMM_SMEM>>>(gj);

    attn_tc<<<dim3(SQ/128, BH), 256, ATTN_SMEM>>>(QhiP, QloP, KhP, KlP, VhP, VlP, Xp);

    GemmJobs go;
    go.A[0] = Xp; go.W[0] = Woc; go.bias[0] = bo; go.C[0] = out; go.C2[0] = nullptr; go.mode[0] = 0;
    go.A[1] = go.A[2] = nullptr; go.W[1] = go.W[2] = nullptr;
    go.bias[1] = go.bias[2] = nullptr; go.C[1] = go.C[2] = nullptr;
    go.C2[1] = go.C2[2] = nullptr; go.mode[1] = go.mode[2] = 0;
    gemm_tf32<<<dim3(DM/128, NTOK/128, 1), 256, GEMM_SMEM>>>(go);
}

// round 9
// speedup vs baseline: 3.8842x; 1.0977x over previous
#include <cuda_runtime.h>
#include <cuda_bf16.h>
#include <math.h>
#include <cstdint>

// Problem constants
#define SQ    2048
#define DM    1024
#define NH    16
#define DKH   64
#define NB    2
#define NTOK  (NB*SQ)   // 4096
#define BH    (NB*NH)   // 32

// ---------------------------------------------------------------------------
// Scratch (no cudaMalloc allowed)
// ---------------------------------------------------------------------------
__device__ uint32_t g_Qhi[(size_t)BH*SQ*32];     // [B,H,S,dk-pairs]
__device__ uint32_t g_Qlo[(size_t)BH*SQ*32];
// K combined: [B,H,S][4 t][4 tig][kh0,kh1,kl0,kl1]  (64 u32 per key)
__device__ uint32_t g_Kc [(size_t)BH*SQ*64];
// V combined: [B,H,dk][32 kt][4 t][4 tig][vh0,vh1,vl0,vl1] (2048 u32 per dk)
__device__ uint32_t g_Vc [(size_t)BH*DKH*32*64];
__device__ float g_X  [(size_t)NTOK*DM];         // attn out, tf32 + k-interleaved
// pre-rounded + k-interleaved fp32(tf32) inputs / weights
__device__ float g_qc [(size_t)NTOK*DM];
__device__ float g_kc [(size_t)NTOK*DM];
__device__ float g_vc [(size_t)NTOK*DM];
__device__ float g_Wqc[(size_t)DM*DM];
__device__ float g_Wkc[(size_t)DM*DM];
__device__ float g_Wvc[(size_t)DM*DM];
__device__ float g_Woc[(size_t)DM*DM];

// ---------------------------------------------------------------------------
// Helpers
// ---------------------------------------------------------------------------
__device__ __forceinline__ uint32_t f2tf32(float f) {
    uint32_t r;
    asm("cvt.rna.tf32.f32 %0, %1;" : "=r"(r) : "f"(f));
    return r;
}
__device__ __forceinline__ float tf32hi(float f) {
    return __uint_as_float(f2tf32(f));
}
__device__ __forceinline__ float ex2(float x) {
    float y;
    asm("ex2.approx.f32 %0, %1;" : "=f"(y) : "f"(x));
    return y;
}
// pack two floats as bf16x2: low half = e, high half = o
__device__ __forceinline__ uint32_t pack_bf16(float e, float o) {
    uint32_t r;
    asm("cvt.rn.bf16x2.f32 %0, %1, %2;" : "=r"(r) : "f"(o), "f"(e));
    return r;
}
__device__ __forceinline__ float blo_f(uint32_t p) { return __uint_as_float(p << 16); }
__device__ __forceinline__ float bhi_f(uint32_t p) { return __uint_as_float(p & 0xffff0000u); }

__device__ __forceinline__ void mma_tf32(float c[4], const uint32_t a[4],
                                         const uint32_t b0, const uint32_t b1) {
    asm volatile(
        "mma.sync.aligned.m16n8k8.row.col.f32.tf32.tf32.f32 "
        "{%0,%1,%2,%3}, {%4,%5,%6,%7}, {%8,%9}, {%0,%1,%2,%3};"
        : "+f"(c[0]), "+f"(c[1]), "+f"(c[2]), "+f"(c[3])
        : "r"(a[0]), "r"(a[1]), "r"(a[2]), "r"(a[3]),
          "r"(b0), "r"(b1));
}
__device__ __forceinline__ void mma_bf16(float c[4], const uint32_t a[4],
                                         const uint32_t b0, const uint32_t b1) {
    asm volatile(
        "mma.sync.aligned.m16n8k16.row.col.f32.bf16.bf16.f32 "
        "{%0,%1,%2,%3}, {%4,%5,%6,%7}, {%8,%9}, {%0,%1,%2,%3};"
        : "+f"(c[0]), "+f"(c[1]), "+f"(c[2]), "+f"(c[3])
        : "r"(a[0]), "r"(a[1]), "r"(a[2]), "r"(a[3]),
          "r"(b0), "r"(b1));
}
__device__ __forceinline__ void cp16(uint32_t saddr, const void* g) {
    asm volatile("cp.async.cg.shared.global [%0], [%1], 16;"
                 :: "r"(saddr), "l"(g) : "memory");
}
#define CP_COMMIT() asm volatile("cp.async.commit_group;" ::: "memory")

__device__ __forceinline__ uint32_t smem_u32(const void* p) {
    uint32_t a;
    asm("{ .reg .u64 t; cvta.to.shared.u64 t, %1; cvt.u32.u64 %0, t; }"
        : "=r"(a) : "l"(p));
    return a;
}

// ---------------------------------------------------------------------------
// Merged tf32 pre-round + k-interleave pass.
// Storage order within each 8-col group: [k0,k4,k1,k5,k2,k6,k3,k7]
// (s(k) = (k&3)*2 + (k>>2)), so fragment pairs (k, k+4) are adjacent.
// ---------------------------------------------------------------------------
struct CvtJobs {
    const float4* src[7];
    float4*       dst[7];
    int           n8[7];   // number of 8-float groups
};

__global__ __launch_bounds__(256)
void cvt_tf32_k(CvtJobs jobs)
{
    const int a = blockIdx.y;
    const int i = blockIdx.x*blockDim.x + threadIdx.x;
    if (i < jobs.n8[a]) {
        float4 lo = jobs.src[a][2*i];
        float4 hi = jobs.src[a][2*i+1];
        float4 d0, d1;
        d0.x = tf32hi(lo.x); d0.y = tf32hi(hi.x);
        d0.z = tf32hi(lo.y); d0.w = tf32hi(hi.y);
        d1.x = tf32hi(lo.z); d1.y = tf32hi(hi.z);
        d1.z = tf32hi(lo.w); d1.w = tf32hi(hi.w);
        jobs.dst[a][2*i]   = d0;
        jobs.dst[a][2*i+1] = d1;
    }
}

// ---------------------------------------------------------------------------
// tf32 mma.sync GEMM, 2-stage cp.async pipeline, k-interleaved inputs,
// LDS.64 fragment loads. Merged jobs (grid.z).
// mode 0: C row-major fp32 [M,N]  (final output)
// mode 1: bf16 hi/lo packed dk-pairs -> C,C2 u32 [B,H,S,32]   (Q)
// mode 4: K combined-interleaved u32 [B,H,S,64]               (K)
// mode 5: V combined-interleaved u16 writes into u32 [B,H,dk,2048] (V)
// ---------------------------------------------------------------------------
#define BK 32
#define KP 40                          // row stride (u32), ≡8 mod 32
#define TILE_WORDS (128*KP)            // 5120
#define STAGE_W    (2*TILE_WORDS)      // 10240
#define GEMM_SMEM  (2*STAGE_W*4)       // 81920 B
#define GEMM_NT    (DM/BK)             // 32

struct GemmJobs {
    const float* A[3];
    const float* W[3];
    const float* bias[3];
    void*        C[3];
    void*        C2[3];
    int          mode[3];
};

__global__ __launch_bounds__(256, 2)
void gemm_tf32(GemmJobs jobs)
{
    extern __shared__ uint32_t sh[];
    const uint32_t smem0 = smem_u32(sh);

    const int z = blockIdx.z;
    const float* __restrict__ A    = jobs.A[z];
    const float* __restrict__ W    = jobs.W[z];
    const float* __restrict__ bias = jobs.bias[z];
    void* C  = jobs.C[z];
    void* C2 = jobs.C2[z];
    const int mode = jobs.mode[z];

    const int tid    = threadIdx.x;
    const int wid    = tid >> 5;
    const int lane   = tid & 31;
    const int gid    = lane >> 2;
    const int tig    = lane & 3;
    const int warp_m = (wid >> 2) * 64;
    const int warp_n = (wid & 3) * 32;
    const int bx     = blockIdx.x;
    const int by     = blockIdx.y;

    const float* Ab = A + (size_t)(by*128)*DM;
    const float* Wb = W + (size_t)(bx*128)*DM;

    auto prefetch = [&](int kt) {
        if (kt < GEMM_NT) {
            const uint32_t base = smem0 + (kt & 1)*(STAGE_W*4);
            #pragma unroll
            for (int t = 0; t < 8; t++) {
                int chunk = tid + t*256;            // 0..2047
                int arr   = chunk >> 10;            // 0=A, 1=B
                int w     = chunk & 1023;
                int row   = w >> 3;
                int kc4   = (w & 7) * 4;
                uint32_t so = (uint32_t)((arr*TILE_WORDS + row*KP + kc4)*4);
                const float* src = (arr ? Wb : Ab) + (size_t)row*DM + kt*BK + kc4;
                cp16(base + so, src);
            }
        }
        CP_COMMIT();
    };

    float acc[4][4][4];
    #pragma unroll
    for (int i = 0; i < 4; i++)
        #pragma unroll
        for (int j = 0; j < 4; j++)
            #pragma unroll
            for (int r = 0; r < 4; r++) acc[i][j][r] = 0.0f;

    prefetch(0);

    for (int kt = 0; kt < GEMM_NT; kt++) {
        prefetch(kt + 1);   // stage (kt+1)&1 freed by trailing barrier of prev iter
        asm volatile("cp.async.wait_group 1;" ::: "memory");
        __syncthreads();

        const uint32_t* a = sh + (kt & 1)*STAGE_W;
        const uint32_t* b = a + TILE_WORDS;

        #pragma unroll
        for (int ks = 0; ks < BK; ks += 8) {
            uint32_t af[4][4], bf[4][2];
            #pragma unroll
            for (int i = 0; i < 4; i++) {
                int r0 = warp_m + i*16 + gid;
                uint2 A0 = *(const uint2*)&a[ r0    *KP + ks + 2*tig];
                uint2 A1 = *(const uint2*)&a[(r0+8) *KP + ks + 2*tig];
                af[i][0] = A0.x; af[i][1] = A1.x;
                af[i][2] = A0.y; af[i][3] = A1.y;
            }
            #pragma unroll
            for (int j = 0; j < 4; j++) {
                int n = warp_n + j*8 + gid;
                uint2 B0 = *(const uint2*)&b[n*KP + ks + 2*tig];
                bf[j][0] = B0.x; bf[j][1] = B0.y;
            }
            #pragma unroll
            for (int i = 0; i < 4; i++)
                #pragma unroll
                for (int j = 0; j < 4; j++)
                    mma_tf32(acc[i][j], af[i], bf[j][0], bf[j][1]);
        }
        __syncthreads();   // free this stage for prefetch(kt+2)
    }

    #pragma unroll
    for (int i = 0; i < 4; i++) {
        #pragma unroll
        for (int j = 0; j < 4; j++) {
            int row0 = by*128 + warp_m + i*16 + gid;
            int row1 = row0 + 8;
            int col  = bx*128 + warp_n + j*8 + tig*2;
            float bx0 = bias[col], bx1 = bias[col+1];
            float v00 = acc[i][j][0] + bx0, v01 = acc[i][j][1] + bx1;
            float v10 = acc[i][j][2] + bx0, v11 = acc[i][j][3] + bx1;
            if (mode == 0) {
                float* Cf = (float*)C;
                *(float2*)(Cf + (size_t)row0*DM + col) = make_float2(v00, v01);
                *(float2*)(Cf + (size_t)row1*DM + col) = make_float2(v10, v11);
            } else if (mode == 1) {
                // Q: bf16 hi/lo packed dk-pairs [B,H,S,32]
                int h = col >> 6, dkp = (col & 63) >> 1;
                int b0r = row0 >> 11, s0 = row0 & (SQ-1);
                int b1r = row1 >> 11, s1 = row1 & (SQ-1);
                size_t o0 = ((size_t)(b0r*NH + h)*SQ + s0)*32 + dkp;
                size_t o1 = ((size_t)(b1r*NH + h)*SQ + s1)*32 + dkp;
                uint32_t h0 = pack_bf16(v00, v01);
                uint32_t h1 = pack_bf16(v10, v11);
                ((uint32_t*)C)[o0] = h0;
                ((uint32_t*)C)[o1] = h1;
                ((uint32_t*)C2)[o0] = pack_bf16(v00 - blo_f(h0), v01 - bhi_f(h0));
                ((uint32_t*)C2)[o1] = pack_bf16(v10 - blo_f(h1), v11 - bhi_f(h1));
            } else if (mode == 4) {
                // K combined: [B,H,S][t*16 + tig*4 + {h0,h1,l0,l1}]
                int h = col >> 6, dkp = (col & 63) >> 1;
                int t = dkp >> 3, p = dkp & 7;
                int tg = p & 3, sl = p >> 2;
                int b0r = row0 >> 11, s0 = row0 & (SQ-1);
                int b1r = row1 >> 11, s1 = row1 & (SQ-1);
                size_t o0 = ((size_t)(b0r*NH + h)*SQ + s0)*64 + t*16 + tg*4 + sl;
                size_t o1 = ((size_t)(b1r*NH + h)*SQ + s1)*64 + t*16 + tg*4 + sl;
                uint32_t h0 = pack_bf16(v00, v01);
                uint32_t h1 = pack_bf16(v10, v11);
                uint32_t* Kc = (uint32_t*)C;
                Kc[o0]     = h0;
                Kc[o0 + 2] = pack_bf16(v00 - blo_f(h0), v01 - bhi_f(h0));
                Kc[o1]     = h1;
                Kc[o1 + 2] = pack_bf16(v10 - blo_f(h1), v11 - bhi_f(h1));
            } else {
                // mode 5: V combined, u16 scatter into [B,H,dk][kt*64 + ...]
                unsigned short* Vc16 = (unsigned short*)C;
                #pragma unroll
                for (int u = 0; u < 4; u++) {
                    int s  = (u < 2) ? row0 : row1;
                    int dk = col + (u & 1);
                    float f = (u == 0) ? v00 : (u == 1) ? v01 : (u == 2) ? v10 : v11;
                    int br = s >> 11; int ss = s & (SQ-1);
                    int h  = dk >> 6; int dkl = dk & 63;
                    int kt = ss >> 6, q = ss & 63;
                    int pp = q >> 1, par = q & 1;
                    int t = pp >> 3, r = pp & 7;
                    int tg = r & 3, sl = r >> 2;
                    size_t u32idx = (((size_t)(br*NH + h)*DKH + dkl)*32 + kt)*64
                                  + t*16 + tg*4 + sl;
                    uint32_t ph = pack_bf16(f, 0.0f);
                    float fh = blo_f(ph);
                    uint32_t pl = pack_bf16(f - fh, 0.0f);
                    Vc16[u32idx*2 + par]       = (unsigned short)(ph & 0xffff);
                    Vc16[(u32idx + 2)*2 + par] = (unsigned short)(pl & 0xffff);
                }
            }
        }
    }
}

// ---------------------------------------------------------------------------
// bf16 tensor-core causal flash attention (3-term compensated splits).
// K/V smem: combined-interleaved rows, stride 80 u32 (≡16 mod 32):
// one LDS.128 yields {h0,h1,l0,l1} per (j,t) fragment group.
// ---------------------------------------------------------------------------
#define AT_RS       80                        // row stride (u32)
#define KV_ROW_W    64                        // payload u32 per row
#define ARR_W       (64*AT_RS)                // 5120 u32 per array
#define STAGE_WORDS (2*ARR_W)                 // 10240 u32 (K + V)
#define ATTN_SMEM   (2*STAGE_WORDS*4)         // 81920 B
#define COEF 0.18033688f                      // 0.125 * log2(e)

__global__ __launch_bounds__(256, 1)
void attn_tc(const uint32_t* __restrict__ Qhi, const uint32_t* __restrict__ Qlo,
             const uint32_t* __restrict__ Kc,  const uint32_t* __restrict__ Vc,
             float* __restrict__ X)
{
    extern __shared__ uint32_t sh[];
    const uint32_t smem0 = smem_u32(sh);

    const int qt   = (int)gridDim.x - 1 - (int)blockIdx.x;  // heavy tiles first
    const int bh   = blockIdx.y;
    const int tid  = threadIdx.x;
    const int wid  = tid >> 5;
    const int lane = tid & 31;
    const int gid  = lane >> 2;
    const int tig  = lane & 3;

    const int row0 = qt*128 + wid*16 + gid;
    const int row1 = row0 + 8;

    // Q fragments (pre-split bf16 pairs) in registers
    uint32_t qh[4][4], ql[4][4];
    {
        const uint32_t* q0h = Qhi + ((size_t)bh*SQ + row0)*32;
        const uint32_t* q1h = Qhi + ((size_t)bh*SQ + row1)*32;
        const uint32_t* q0l = Qlo + ((size_t)bh*SQ + row0)*32;
        const uint32_t* q1l = Qlo + ((size_t)bh*SQ + row1)*32;
        #pragma unroll
        for (int t = 0; t < 4; t++) {
            qh[t][0] = q0h[8*t + tig];     qh[t][1] = q1h[8*t + tig];
            qh[t][2] = q0h[8*t + tig + 4]; qh[t][3] = q1h[8*t + tig + 4];
            ql[t][0] = q0l[8*t + tig];     ql[t][1] = q1l[8*t + tig];
            ql[t][2] = q0l[8*t + tig + 4]; ql[t][3] = q1l[8*t + tig + 4];
        }
    }

    float o[8][4];
    #pragma unroll
    for (int j = 0; j < 8; j++)
        #pragma unroll
        for (int r = 0; r < 4; r++) o[j][r] = 0.0f;
    float m0 = -INFINITY, m1 = -INFINITY, l0 = 0.0f, l1 = 0.0f;

    const uint32_t* KcG = Kc + (size_t)bh*SQ*64;
    const uint32_t* VcG = Vc + (size_t)bh*DKH*32*64;

    auto prefetch = [&](int kt, int st) {
        const uint32_t base = smem0 + st*(STAGE_WORDS*4);
        #pragma unroll
        for (int t = 0; t < 8; t++) {
            int chunk = tid + t*256;         // 0..2047
            int arr   = chunk >> 10;         // 0=K, 1=V
            int w     = chunk & 1023;
            int row   = w >> 4;              // 0..63
            int ch    = (w & 15) * 4;        // u32 offset within payload
            uint32_t saddr = base + (uint32_t)((arr*ARR_W + row*AT_RS + ch)*4);
            const uint32_t* src = arr
                ? VcG + (size_t)row*2048 + kt*64 + ch
                : KcG + (size_t)(kt*64 + row)*64 + ch;
            cp16(saddr, src);
        }
        CP_COMMIT();
    };

    const int ktmax = 2*qt + 1;
    prefetch(0, 0);

    for (int kt = 0; kt <= ktmax; kt++) {
        const int st = kt & 1;
        asm volatile("cp.async.wait_group 0;" ::: "memory");
        __syncthreads();
        if (kt < ktmax) prefetch(kt + 1, st ^ 1);

        const uint32_t* sK = sh + st*STAGE_WORDS;
        const uint32_t* sV = sK + ARR_W;

        // S = Q K^T  (3-term bf16)
        float sc[8][4];
        #pragma unroll
        for (int j = 0; j < 8; j++)
            #pragma unroll
            for (int r = 0; r < 4; r++) sc[j][r] = 0.0f;

        #pragma unroll
        for (int j = 0; j < 8; j++) {
            const int nrow = (8*j + gid)*AT_RS + tig*4;
            #pragma unroll
            for (int t = 0; t < 4; t++) {
                uint4 kc = *(const uint4*)&sK[nrow + t*16];
                mma_bf16(sc[j], qh[t], kc.x, kc.y);
                mma_bf16(sc[j], qh[t], kc.z, kc.w);
                mma_bf16(sc[j], ql[t], kc.x, kc.y);
            }
        }

        // Causal mask
        if (kt*64 + 63 > row0) {
            #pragma unroll
            for (int j = 0; j < 8; j++) {
                int col = kt*64 + 8*j + 2*tig;
                if (col     > row0) sc[j][0] = -1e30f;
                if (col + 1 > row0) sc[j][1] = -1e30f;
                if (col     > row1) sc[j][2] = -1e30f;
                if (col + 1 > row1) sc[j][3] = -1e30f;
            }
        }

        // Online softmax
        float mx0 = -INFINITY, mx1 = -INFINITY;
        #pragma unroll
        for (int j = 0; j < 8; j++) {
            mx0 = fmaxf(mx0, fmaxf(sc[j][0], sc[j][1]));
            mx1 = fmaxf(mx1, fmaxf(sc[j][2], sc[j][3]));
        }
        #pragma unroll
        for (int off = 1; off <= 2; off <<= 1) {
            mx0 = fmaxf(mx0, __shfl_xor_sync(0xffffffffu, mx0, off));
            mx1 = fmaxf(mx1, __shfl_xor_sync(0xffffffffu, mx1, off));
        }
        float mn0 = fmaxf(m0, mx0), mn1 = fmaxf(m1, mx1);
        float a0 = ex2((m0 - mn0)*COEF), a1 = ex2((m1 - mn1)*COEF);
        m0 = mn0; m1 = mn1;

        float ls0 = 0.0f, ls1 = 0.0f;
        #pragma unroll
        for (int j = 0; j < 8; j++) {
            sc[j][0] = ex2((sc[j][0] - m0)*COEF);
            sc[j][1] = ex2((sc[j][1] - m0)*COEF);
            sc[j][2] = ex2((sc[j][2] - m1)*COEF);
            sc[j][3] = ex2((sc[j][3] - m1)*COEF);
            ls0 += sc[j][0] + sc[j][1];
            ls1 += sc[j][2] + sc[j][3];
        }
        #pragma unroll
        for (int off = 1; off <= 2; off <<= 1) {
            ls0 += __shfl_xor_sync(0xffffffffu, ls0, off);
            ls1 += __shfl_xor_sync(0xffffffffu, ls1, off);
        }
        l0 = l0*a0 + ls0;
        l1 = l1*a1 + ls1;
        #pragma unroll
        for (int j = 0; j < 8; j++) {
            o[j][0] *= a0; o[j][1] *= a0;
            o[j][2] *= a1; o[j][3] *= a1;
        }

        // P: accumulator pairs -> k16 A fragments via bf16x2 packing (no shfl)
        uint32_t ph[4][4], pl[4][4];
        #pragma unroll
        for (int t = 0; t < 4; t++) {
            uint32_t h;
            h = pack_bf16(sc[2*t][0],   sc[2*t][1]);
            ph[t][0] = h;
            pl[t][0] = pack_bf16(sc[2*t][0]   - blo_f(h), sc[2*t][1]   - bhi_f(h));
            h = pack_bf16(sc[2*t][2],   sc[2*t][3]);
            ph[t][1] = h;
            pl[t][1] = pack_bf16(sc[2*t][2]   - blo_f(h), sc[2*t][3]   - bhi_f(h));
            h = pack_bf16(sc[2*t+1][0], sc[2*t+1][1]);
            ph[t][2] = h;
            pl[t][2] = pack_bf16(sc[2*t+1][0] - blo_f(h), sc[2*t+1][1] - bhi_f(h));
            h = pack_bf16(sc[2*t+1][2], sc[2*t+1][3]);
            ph[t][3] = h;
            pl[t][3] = pack_bf16(sc[2*t+1][2] - blo_f(h), sc[2*t+1][3] - bhi_f(h));
        }

        // O += P V  (3-term bf16)
        #pragma unroll
        for (int j = 0; j < 8; j++) {
            const int nrow = (8*j + gid)*AT_RS + tig*4;
            #pragma unroll
            for (int t = 0; t < 4; t++) {
                uint4 vc = *(const uint4*)&sV[nrow + t*16];
                mma_bf16(o[j], ph[t], vc.x, vc.y);
                mma_bf16(o[j], ph[t], vc.z, vc.w);
                mma_bf16(o[j], pl[t], vc.x, vc.y);
            }
        }
    }

    // Finalize: write X pre-rounded tf32, k-interleaved for the Wo GEMM
    const float inv0 = 1.0f / l0, inv1 = 1.0f / l1;
    const int b = bh >> 4, h = bh & 15;
    float* x0 = X + ((size_t)(b*SQ + row0))*DM + h*DKH;
    float* x1 = X + ((size_t)(b*SQ + row1))*DM + h*DKH;
    const int off0 = (tig < 2) ? 4*tig : 4*tig - 7;   // storage of col 2*tig
    #pragma unroll
    for (int j = 0; j < 8; j++) {
        int base = 8*j + off0;
        x0[base]     = tf32hi(o[j][0]*inv0);
        x0[base + 2] = tf32hi(o[j][1]*inv0);
        x1[base]     = tf32hi(o[j][2]*inv1);
        x1[base + 2] = tf32hi(o[j][3]*inv1);
    }
}

// ---------------------------------------------------------------------------
// Launch
// ---------------------------------------------------------------------------
extern "C" void kernel_launch(void* const* d_in, const int* in_sizes, int n_in,
                              void* d_out, int out_size)
{
    (void)in_sizes; (void)n_in; (void)out_size;
    const float* q  = (const float*)d_in[0];
    const float* k  = (const float*)d_in[1];
    const float* v  = (const float*)d_in[2];
    const float* Wq = (const float*)d_in[4];
    const float* bq = (const float*)d_in[5];
    const float* Wk = (const float*)d_in[6];
    const float* bk = (const float*)d_in[7];
    const float* Wv = (const float*)d_in[8];
    const float* bv = (const float*)d_in[9];
    const float* Wo = (const float*)d_in[10];
    const float* bo = (const float*)d_in[11];
    float* out = (float*)d_out;

    uint32_t *QhiP, *QloP, *KcP, *VcP;
    float *Xp, *qc, *kc, *vc, *Wqc, *Wkc, *Wvc, *Woc;
    cudaGetSymbolAddress((void**)&QhiP, g_Qhi);
    cudaGetSymbolAddress((void**)&QloP, g_Qlo);
    cudaGetSymbolAddress((void**)&KcP,  g_Kc);
    cudaGetSymbolAddress((void**)&VcP,  g_Vc);
    cudaGetSymbolAddress((void**)&Xp,   g_X);
    cudaGetSymbolAddress((void**)&qc,   g_qc);
    cudaGetSymbolAddress((void**)&kc,   g_kc);
    cudaGetSymbolAddress((void**)&vc,   g_vc);
    cudaGetSymbolAddress((void**)&Wqc,  g_Wqc);
    cudaGetSymbolAddress((void**)&Wkc,  g_Wkc);
    cudaGetSymbolAddress((void**)&Wvc,  g_Wvc);
    cudaGetSymbolAddress((void**)&Woc,  g_Woc);

    cudaFuncSetAttribute(gemm_tf32,
                         cudaFuncAttributeMaxDynamicSharedMemorySize, GEMM_SMEM);
    cudaFuncSetAttribute(attn_tc,
                         cudaFuncAttributeMaxDynamicSharedMemorySize, ATTN_SMEM);

    const int nA8 = NTOK*DM/8;    // 524288
    const int nW8 = DM*DM/8;      // 131072

    CvtJobs cj;
    cj.src[0] = (const float4*)q;  cj.dst[0] = (float4*)qc;  cj.n8[0] = nA8;
    cj.src[1] = (const float4*)k;  cj.dst[1] = (float4*)kc;  cj.n8[1] = nA8;
    cj.src[2] = (const float4*)v;  cj.dst[2] = (float4*)vc;  cj.n8[2] = nA8;
    cj.src[3] = (const float4*)Wq; cj.dst[3] = (float4*)Wqc; cj.n8[3] = nW8;
    cj.src[4] = (const float4*)Wk; cj.dst[4] = (float4*)Wkc; cj.n8[4] = nW8;
    cj.src[5] = (const float4*)Wv; cj.dst[5] = (float4*)Wvc; cj.n8[5] = nW8;
    cj.src[6] = (const float4*)Wo; cj.dst[6] = (float4*)Woc; cj.n8[6] = nW8;
    cvt_tf32_k<<<dim3(nA8/256, 7), 256>>>(cj);

    GemmJobs gj;
    gj.A[0] = qc; gj.W[0] = Wqc; gj.bias[0] = bq; gj.C[0] = QhiP; gj.C2[0] = QloP;   gj.mode[0] = 1;
    gj.A[1] = kc; gj.W[1] = Wkc; gj.bias[1] = bk; gj.C[1] = KcP;  gj.C2[1] = nullptr; gj.mode[1] = 4;
    gj.A[2] = vc; gj.W[2] = Wvc; gj.bias[2] = bv; gj.C[2] = VcP;  gj.C2[2] = nullptr; gj.mode[2] = 5;
    gemm_tf32<<<dim3(DM/128, NTOK/128, 3), 256, GEMM_SMEM>>>(gj);

    attn_tc<<<dim3(SQ/128, BH), 256, ATTN_SMEM>>>(QhiP, QloP, KcP, VcP, Xp);

    GemmJobs go;
    go.A[0] = Xp; go.W[0] = Woc; go.bias[0] = bo; go.C[0] = out; go.C2[0] = nullptr; go.mode[0] = 0;
    go.A[1] = go.A[2] = nullptr; go.W[1] = go.W[2] = nullptr;
    go.bias[1] = go.bias[2] = nullptr; go.C[1] = go.C[2] = nullptr;
    go.C2[1] = go.C2[2] = nullptr; go.mode[1] = go.mode[2] = 0;
    gemm_tf32<<<dim3(DM/128, NTOK/128, 1), 256, GEMM_SMEM>>>(go);
}